// round 13
// baseline (speedup 1.0000x reference)
#include <cuda_runtime.h>
#include <cuda_bf16.h>
#include <mma.h>
#include <math.h>
#include <cstdint>

using namespace nvcuda;

// ---------------- problem constants ----------------
#define HDIM 128                 // F_IN == H == 128
#define MAXN 50048               // 391 * 128, padded node count
#define MAXNNZ 700000
#define NFEAT_PAD (MAXN * HDIM)

// ---------------- device scratch (allocation-free) ----------------
__device__ float g_deg[MAXN];
__device__ float g_dinv[MAXN];
__device__ int   g_cnt[MAXN];
__device__ int   g_off[MAXN + 1];
__device__ int   g_fill[MAXN];
__device__ int   g_src[MAXNNZ];
__device__ float g_wc[MAXNNZ];
__device__ float g_h[NFEAT_PAD];
__device__ float g_h0[NFEAT_PAD];
__device__ float g_ag[NFEAT_PAD];
__device__ int   g_bsum[64];
__device__ int   g_boff[65];

// ---------------- cp.async helpers ----------------
__device__ __forceinline__ void cp_async16(void* smem, const void* gmem) {
    unsigned int s = (unsigned int)__cvta_generic_to_shared(smem);
    asm volatile("cp.async.cg.shared.global [%0], [%1], 16;\n" :: "r"(s), "l"(gmem));
}
#define CP_COMMIT() asm volatile("cp.async.commit_group;\n" ::: "memory")
#define CP_WAIT(n)  asm volatile("cp.async.wait_group %0;\n" :: "n"(n) : "memory")

// ---------------- graph preprocessing ----------------
__global__ void init_kernel(float* deg, int* cnt, int n) {
    int i = blockIdx.x * blockDim.x + threadIdx.x;
    if (i < n) { deg[i] = 1.0f; cnt[i] = 1; }   // self-loop weight 1, self in-edge
}

__global__ void edge_count_kernel(const int* __restrict__ row, const int* __restrict__ col,
                                  const float* __restrict__ w, float* deg, int* cnt, int E) {
    int e = blockIdx.x * blockDim.x + threadIdx.x;
    if (e < E) {
        atomicAdd(&deg[row[e]], w[e]);
        atomicAdd(&cnt[col[e]], 1);
    }
}

__global__ void dinv_kernel(const float* __restrict__ deg, float* dinv, int n) {
    int i = blockIdx.x * blockDim.x + threadIdx.x;
    if (i < n) dinv[i] = rsqrtf(deg[i]);   // deg >= 1 always
}

// ---- multi-block exclusive scan: per-block scan -> scan of block sums -> fixup ----
__global__ void scan_block_kernel(const int* __restrict__ cnt, int* off, int n) {
    __shared__ int sm[1024];
    int i = blockIdx.x * 1024 + threadIdx.x;
    int v = (i < n) ? cnt[i] : 0;
    sm[threadIdx.x] = v;
    __syncthreads();
#pragma unroll
    for (int d = 1; d < 1024; d <<= 1) {
        int t = (threadIdx.x >= d) ? sm[threadIdx.x - d] : 0;
        __syncthreads();
        sm[threadIdx.x] += t;
        __syncthreads();
    }
    if (i < n) off[i] = sm[threadIdx.x] - v;     // exclusive within block
    if (threadIdx.x == 1023) g_bsum[blockIdx.x] = sm[1023];
}

__global__ void scan_bsums_kernel(int nb) {
    if (threadIdx.x == 0) {
        int acc = 0;
        for (int b = 0; b < nb; b++) { g_boff[b] = acc; acc += g_bsum[b]; }
        g_boff[nb] = acc;
    }
}

__global__ void scan_fixup_kernel(int* off, int* fill, int n, int nb) {
    int i = blockIdx.x * 1024 + threadIdx.x;
    if (i < n) {
        int o = off[i] + g_boff[blockIdx.x];
        off[i] = o; fill[i] = o;
    }
    if (i == 0) off[n] = g_boff[nb];
}

__global__ void fill_edges_kernel(const int* __restrict__ row, const int* __restrict__ col,
                                  const float* __restrict__ w, const float* __restrict__ dinv,
                                  int* fill, int* srcv, float* wcsc, int E) {
    int e = blockIdx.x * blockDim.x + threadIdx.x;
    if (e < E) {
        int r = row[e], c = col[e];
        int p = atomicAdd(&fill[c], 1);
        srcv[p] = r;
        wcsc[p] = dinv[r] * w[e] * dinv[c];
    }
}

__global__ void fill_self_kernel(const float* __restrict__ dinv, int* fill,
                                 int* srcv, float* wcsc, int n) {
    int i = blockIdx.x * blockDim.x + threadIdx.x;
    if (i < n) {
        int p = atomicAdd(&fill[i], 1);
        srcv[p] = i;
        wcsc[p] = dinv[i] * dinv[i];
    }
}

// zero padding rows [N, MAXN) of h, h0, ag so guard-free GEMMs read zeros
__global__ void pad_kernel(float* h, float* h0, float* ag, int startElem, int totalElem) {
    int i = blockIdx.x * blockDim.x + threadIdx.x + startElem;
    if (i < totalElem) { h[i] = 0.0f; h0[i] = 0.0f; ag[i] = 0.0f; }
}

// ---------------- fp32 SGEMM tiles (input / output linears) ----------------
#define BM 128
#define BN 128
#define BK 8
#define TM 8
#define TN 8

// ---- input linear: h = h0 = relu(x @ w_in + b), guarded (x has exactly M rows) ----
__global__ void __launch_bounds__(256, 2)
gemm_in(const float* __restrict__ A, const float* __restrict__ W,
        const float* __restrict__ bias, float* __restrict__ out,
        float* __restrict__ out2, int M) {
    __shared__ float As[BK][BM];
    __shared__ float Bs[BK][BN];
    const int tid = threadIdx.x;
    const int tx = tid & 15, ty = tid >> 4;
    const int m0 = blockIdx.x * BM;
    const int arow = tid >> 1, acol4 = (tid & 1) * 4;
    const int brow = tid >> 5, bcol4 = (tid & 31) * 4;

    float acc[TM][TN];
#pragma unroll
    for (int i = 0; i < TM; i++)
#pragma unroll
        for (int j = 0; j < TN; j++) acc[i][j] = 0.0f;

    for (int k0 = 0; k0 < HDIM; k0 += BK) {
        float4 av = make_float4(0.f, 0.f, 0.f, 0.f);
        int am = m0 + arow;
        if (am < M) av = *reinterpret_cast<const float4*>(A + (size_t)am * HDIM + k0 + acol4);
        As[acol4 + 0][arow] = av.x; As[acol4 + 1][arow] = av.y;
        As[acol4 + 2][arow] = av.z; As[acol4 + 3][arow] = av.w;

        float4 bv = *reinterpret_cast<const float4*>(W + (size_t)(k0 + brow) * HDIM + bcol4);
        Bs[brow][bcol4 + 0] = bv.x; Bs[brow][bcol4 + 1] = bv.y;
        Bs[brow][bcol4 + 2] = bv.z; Bs[brow][bcol4 + 3] = bv.w;
        __syncthreads();

#pragma unroll
        for (int kk = 0; kk < BK; kk++) {
            float ra[TM], rb[TN];
#pragma unroll
            for (int i = 0; i < TM; i++) ra[i] = As[kk][ty * TM + i];
#pragma unroll
            for (int j = 0; j < TN; j++) rb[j] = Bs[kk][tx * TN + j];
#pragma unroll
            for (int i = 0; i < TM; i++)
#pragma unroll
                for (int j = 0; j < TN; j++) acc[i][j] += ra[i] * rb[j];
        }
        __syncthreads();
    }

    float b0[TN];
#pragma unroll
    for (int j = 0; j < TN; j++) b0[j] = bias[tx * TN + j];

#pragma unroll
    for (int i = 0; i < TM; i++) {
        int m = m0 + ty * TM + i;
        if (m >= M) continue;
        float4 o0, o1;
        o0.x = fmaxf(acc[i][0] + b0[0], 0.f); o0.y = fmaxf(acc[i][1] + b0[1], 0.f);
        o0.z = fmaxf(acc[i][2] + b0[2], 0.f); o0.w = fmaxf(acc[i][3] + b0[3], 0.f);
        o1.x = fmaxf(acc[i][4] + b0[4], 0.f); o1.y = fmaxf(acc[i][5] + b0[5], 0.f);
        o1.z = fmaxf(acc[i][6] + b0[6], 0.f); o1.w = fmaxf(acc[i][7] + b0[7], 0.f);
        float4* p  = reinterpret_cast<float4*>(out  + (size_t)m * HDIM + tx * TN);
        float4* p2 = reinterpret_cast<float4*>(out2 + (size_t)m * HDIM + tx * TN);
        p[0] = o0; p[1] = o1; p2[0] = o0; p2[1] = o1;
    }
}

// ---- output linear: out[M,64] = h @ w_out + b_out ----
__global__ void __launch_bounds__(256, 2)
gemm_out(const float* __restrict__ A, const float* __restrict__ W,
         const float* __restrict__ bias, float* __restrict__ out, int M) {
    __shared__ float As[BK][BM];
    __shared__ float Bs[BK][BN];
    const int tid = threadIdx.x;
    const int tx = tid & 15, ty = tid >> 4;
    const int m0 = blockIdx.x * BM;
    const int arow = tid >> 1, acol4 = (tid & 1) * 4;
    const int brow = tid >> 5, bcol4 = (tid & 31) * 4;
    const int Nn = 64;

    float acc[TM][TN];
#pragma unroll
    for (int i = 0; i < TM; i++)
#pragma unroll
        for (int j = 0; j < TN; j++) acc[i][j] = 0.0f;

    for (int k0 = 0; k0 < HDIM; k0 += BK) {
        float4 av = *reinterpret_cast<const float4*>(A + (size_t)(m0 + arow) * HDIM + k0 + acol4);
        As[acol4 + 0][arow] = av.x; As[acol4 + 1][arow] = av.y;
        As[acol4 + 2][arow] = av.z; As[acol4 + 3][arow] = av.w;

        float4 bv = make_float4(0.f, 0.f, 0.f, 0.f);
        if (bcol4 < Nn) bv = *reinterpret_cast<const float4*>(W + (size_t)(k0 + brow) * Nn + bcol4);
        Bs[brow][bcol4 + 0] = bv.x; Bs[brow][bcol4 + 1] = bv.y;
        Bs[brow][bcol4 + 2] = bv.z; Bs[brow][bcol4 + 3] = bv.w;
        __syncthreads();

#pragma unroll
        for (int kk = 0; kk < BK; kk++) {
            float ra[TM], rb[TN];
#pragma unroll
            for (int i = 0; i < TM; i++) ra[i] = As[kk][ty * TM + i];
#pragma unroll
            for (int j = 0; j < TN; j++) rb[j] = Bs[kk][tx * TN + j];
#pragma unroll
            for (int i = 0; i < TM; i++)
#pragma unroll
                for (int j = 0; j < TN; j++) acc[i][j] += ra[i] * rb[j];
        }
        __syncthreads();
    }

    if (tx < 8) {   // only columns < 64
        float b0[TN];
#pragma unroll
        for (int j = 0; j < TN; j++) b0[j] = bias[tx * TN + j];
#pragma unroll
        for (int i = 0; i < TM; i++) {
            int m = m0 + ty * TM + i;
            if (m >= M) continue;
            float4 o0, o1;
            o0.x = acc[i][0] + b0[0]; o0.y = acc[i][1] + b0[1];
            o0.z = acc[i][2] + b0[2]; o0.w = acc[i][3] + b0[3];
            o1.x = acc[i][4] + b0[4]; o1.y = acc[i][5] + b0[5];
            o1.z = acc[i][6] + b0[6]; o1.w = acc[i][7] + b0[7];
            float4* p = reinterpret_cast<float4*>(out + (size_t)m * Nn + tx * TN);
            p[0] = o0; p[1] = o1;
        }
    }
}

// ---------------- tf32 tensor-core fused layer GEMM (cp.async 2-stage pipeline) ----
// h_out = relu( beta * ( (cs/beta)*ag + (ci/beta)*h0 + ag@W1 + h0@W2 ) )
// CTA: 128x128 tile, 8 warps 4x2; warp tile 32x64 = 2x4 wmma 16x16 frags.
// 16 k-tiles of 16 (2 halves x 8), double-buffered via cp.async.cg.
// Static smem: 2*(128*24 + 16*136)*4 = 41984 B.
#define SA_LD 24     // A tile leading dim (16 k + 8 pad)
#define SB_LD 136    // B tile leading dim (128 n + 8 pad)
#define NKT 16       // total k-tiles

__global__ void __launch_bounds__(256)
gemm_layer_tc(const float* __restrict__ ag, const float* __restrict__ h0,
              const float* __restrict__ W1, const float* __restrict__ W2,
              float* __restrict__ hout, float csb, float cib, float beta) {
    __shared__ float sA[2][128 * SA_LD];
    __shared__ float sB[2][16 * SB_LD];

    const int tid = threadIdx.x;
    const int wid = tid >> 5;
    const int warp_m = wid >> 1;          // 0..3
    const int warp_n = wid & 1;           // 0..1
    const int m0 = blockIdx.x * 128;

    // tile-load thread mapping
    const int a_row = tid >> 1, a_seg = (tid & 1) * 8;        // A: 2 thr/row, 8 floats each
    const int b_row = tid >> 4, b_col = (tid & 15) * 8;       // B: 16 thr/row, 8 floats each

    const float* Ab[2] = { ag + (size_t)m0 * HDIM, h0 + (size_t)m0 * HDIM };
    const float* Wb[2] = { W1, W2 };

    // prefetch k-tile kt into stage st
    auto prefetch = [&](int st, int kt) {
        int half = kt >> 3;
        int k0 = (kt & 7) * 16;
        const float* Asrc = Ab[half] + (size_t)a_row * HDIM + k0 + a_seg;
        float* Adst = &sA[st][a_row * SA_LD + a_seg];
        cp_async16(Adst,     Asrc);
        cp_async16(Adst + 4, Asrc + 4);
        const float* Bsrc = Wb[half] + (size_t)(k0 + b_row) * HDIM + b_col;
        float* Bdst = &sB[st][b_row * SB_LD + b_col];
        cp_async16(Bdst,     Bsrc);
        cp_async16(Bdst + 4, Bsrc + 4);
    };

    prefetch(0, 0);
    CP_COMMIT();

    // ---- init accumulators with scaled residual: (cs/beta)*ag + (ci/beta)*h0 ----
    // (overlaps with the first cp.async in flight)
    wmma::fragment<wmma::accumulator, 16, 16, 8, float> C[2][4];
#pragma unroll
    for (int mi = 0; mi < 2; mi++) {
        const size_t rbase = (size_t)(m0 + warp_m * 32 + mi * 16) * HDIM;
#pragma unroll
        for (int ni = 0; ni < 4; ni++) {
            const int coff = warp_n * 64 + ni * 16;
            wmma::fragment<wmma::accumulator, 16, 16, 8, float> Ra, Rb;
            wmma::load_matrix_sync(Ra, ag + rbase + coff, HDIM, wmma::mem_row_major);
            wmma::load_matrix_sync(Rb, h0 + rbase + coff, HDIM, wmma::mem_row_major);
#pragma unroll
            for (int t = 0; t < Ra.num_elements; t++)
                C[mi][ni].x[t] = csb * Ra.x[t] + cib * Rb.x[t];
        }
    }

#pragma unroll 1
    for (int kt = 0; kt < NKT; kt++) {
        const int s = kt & 1;
        if (kt + 1 < NKT) {
            prefetch(s ^ 1, kt + 1);
            CP_COMMIT();
            CP_WAIT(1);
        } else {
            CP_WAIT(0);
        }
        __syncthreads();

#pragma unroll
        for (int kk = 0; kk < 16; kk += 8) {
            wmma::fragment<wmma::matrix_a, 16, 16, 8, wmma::precision::tf32, wmma::row_major> a[2];
#pragma unroll
            for (int mi = 0; mi < 2; mi++) {
                wmma::load_matrix_sync(a[mi], &sA[s][(warp_m * 32 + mi * 16) * SA_LD + kk], SA_LD);
#pragma unroll
                for (int t = 0; t < a[mi].num_elements; t++)
                    a[mi].x[t] = wmma::__float_to_tf32(a[mi].x[t]);
            }
#pragma unroll
            for (int ni = 0; ni < 4; ni++) {
                wmma::fragment<wmma::matrix_b, 16, 16, 8, wmma::precision::tf32, wmma::row_major> b;
                wmma::load_matrix_sync(b, &sB[s][kk * SB_LD + warp_n * 64 + ni * 16], SB_LD);
#pragma unroll
                for (int t = 0; t < b.num_elements; t++)
                    b.x[t] = wmma::__float_to_tf32(b.x[t]);
#pragma unroll
                for (int mi = 0; mi < 2; mi++)
                    wmma::mma_sync(C[mi][ni], a[mi], b, C[mi][ni]);
            }
        }
        __syncthreads();
    }

    // ---- epilogue: scale by beta, relu, store straight to global ----
#pragma unroll
    for (int mi = 0; mi < 2; mi++) {
        const size_t rbase = (size_t)(m0 + warp_m * 32 + mi * 16) * HDIM;
#pragma unroll
        for (int ni = 0; ni < 4; ni++) {
#pragma unroll
            for (int t = 0; t < C[mi][ni].num_elements; t++)
                C[mi][ni].x[t] = fmaxf(beta * C[mi][ni].x[t], 0.0f);
            wmma::store_matrix_sync(hout + rbase + warp_n * 64 + ni * 16,
                                    C[mi][ni], HDIM, wmma::mem_row_major);
        }
    }
}

// ---------------- atomic-free CSC aggregation: ag[c,:] = sum_j wc[j]*h[src[j],:] ----
__global__ void agg_kernel(const float* __restrict__ h,
                           const int* __restrict__ off, const int* __restrict__ src,
                           const float* __restrict__ wc, float* __restrict__ ag, int n) {
    int node = (blockIdx.x * blockDim.x + threadIdx.x) >> 5;
    int lane = threadIdx.x & 31;
    if (node >= n) return;
    int s = off[node], e = off[node + 1];
    const float4* H4 = reinterpret_cast<const float4*>(h);
    float4 acc = make_float4(0.f, 0.f, 0.f, 0.f);
    int j = s;
    for (; j + 1 < e; j += 2) {
        int s0 = src[j], s1 = src[j + 1];
        float w0 = wc[j], w1 = wc[j + 1];
        float4 v0 = H4[(size_t)s0 * 32 + lane];
        float4 v1 = H4[(size_t)s1 * 32 + lane];
        acc.x += w0 * v0.x; acc.y += w0 * v0.y; acc.z += w0 * v0.z; acc.w += w0 * v0.w;
        acc.x += w1 * v1.x; acc.y += w1 * v1.y; acc.z += w1 * v1.z; acc.w += w1 * v1.w;
    }
    if (j < e) {
        float w0 = wc[j];
        float4 v0 = H4[(size_t)src[j] * 32 + lane];
        acc.x += w0 * v0.x; acc.y += w0 * v0.y; acc.z += w0 * v0.z; acc.w += w0 * v0.w;
    }
    reinterpret_cast<float4*>(ag)[(size_t)node * 32 + lane] = acc;
}

// ---------------- log_softmax over 64 classes, in place ----------------
__global__ void logsoftmax64_kernel(float* __restrict__ out, int n) {
    int row = blockIdx.x * 8 + (threadIdx.x >> 5);
    int lane = threadIdx.x & 31;
    if (row >= n) return;
    float* p = out + (size_t)row * 64;
    float a = p[lane], b = p[lane + 32];
    float mx = fmaxf(a, b);
#pragma unroll
    for (int d = 16; d; d >>= 1) mx = fmaxf(mx, __shfl_xor_sync(0xFFFFFFFFu, mx, d));
    float s = __expf(a - mx) + __expf(b - mx);
#pragma unroll
    for (int d = 16; d; d >>= 1) s += __shfl_xor_sync(0xFFFFFFFFu, s, d);
    float lse = mx + __logf(s);
    p[lane] = a - lse;
    p[lane + 32] = b - lse;
}

// ---------------- launch ----------------
extern "C" void kernel_launch(void* const* d_in, const int* in_sizes, int n_in,
                              void* d_out, int out_size) {
    const float* x     = (const float*)d_in[0];
    const int*   ei    = (const int*)  d_in[1];
    const float* ew    = (const float*)d_in[2];
    const float* w_in  = (const float*)d_in[3];
    const float* b_in  = (const float*)d_in[4];
    const float* ws1   = (const float*)d_in[5];
    const float* ws2   = (const float*)d_in[6];
    const float* w_out = (const float*)d_in[7];
    const float* b_out = (const float*)d_in[8];

    const int N = in_sizes[0] / HDIM;            // 50000
    const int E = in_sizes[2];                   // 640000
    const int L = in_sizes[5] / (HDIM * HDIM);   // 16
    const float ALPHA = 0.1f;
    const double LAMDA = 0.5;

    const int* erow = ei;
    const int* ecol = ei + E;

    float *deg, *dinv, *wc, *h, *h0, *ag;
    int *cnt, *off, *fill, *src;
    cudaGetSymbolAddress((void**)&deg,  g_deg);
    cudaGetSymbolAddress((void**)&dinv, g_dinv);
    cudaGetSymbolAddress((void**)&cnt,  g_cnt);
    cudaGetSymbolAddress((void**)&off,  g_off);
    cudaGetSymbolAddress((void**)&fill, g_fill);
    cudaGetSymbolAddress((void**)&src,  g_src);
    cudaGetSymbolAddress((void**)&wc,   g_wc);
    cudaGetSymbolAddress((void**)&h,    g_h);
    cudaGetSymbolAddress((void**)&h0,   g_h0);
    cudaGetSymbolAddress((void**)&ag,   g_ag);

    const int TB = 256;
    const int gN = (N + TB - 1) / TB;
    const int gE = (E + TB - 1) / TB;
    const int nb = (N + 1023) / 1024;            // 49 scan blocks

    // ---- graph normalization + CSC build ----
    init_kernel<<<gN, TB>>>(deg, cnt, N);
    edge_count_kernel<<<gE, TB>>>(erow, ecol, ew, deg, cnt, E);
    dinv_kernel<<<gN, TB>>>(deg, dinv, N);
    scan_block_kernel<<<nb, 1024>>>(cnt, off, N);
    scan_bsums_kernel<<<1, 32>>>(nb);
    scan_fixup_kernel<<<nb, 1024>>>(off, fill, N, nb);
    fill_edges_kernel<<<gE, TB>>>(erow, ecol, ew, dinv, fill, src, wc, E);
    fill_self_kernel<<<gN, TB>>>(dinv, fill, src, wc, N);

    // zero padding rows of h/h0/ag
    {
        int startElem = N * HDIM;
        int padElems = NFEAT_PAD - startElem;
        pad_kernel<<<(padElems + TB - 1) / TB, TB>>>(h, h0, ag, startElem, NFEAT_PAD);
    }

    const int gGemm = MAXN / BM;   // 391, covers padded rows

    // ---- input linear + relu; h and h0 (guarded on M=N) ----
    gemm_in<<<gGemm, 256>>>(x, w_in, b_in, h, h0, N);

    // ---- GCNII layers: ag = A_hat@h, then fused tf32 K=256 GEMM ----
    for (int i = 0; i < L; i++) {
        float beta = (float)log(LAMDA / (double)(i + 1) + 1.0);
        float cs = (1.0f - beta) * (1.0f - ALPHA);
        float ci = (1.0f - beta) * ALPHA;
        agg_kernel<<<(N * 32 + 255) / 256, 256>>>(h, off, src, wc, ag, N);
        gemm_layer_tc<<<gGemm, 256>>>(ag, h0,
                                      ws1 + (size_t)i * HDIM * HDIM,
                                      ws2 + (size_t)i * HDIM * HDIM,
                                      h, cs / beta, ci / beta, beta);
    }

    // ---- output linear + log_softmax ----
    float* outp = (float*)d_out;
    gemm_out<<<gGemm, 256>>>(h, w_out, b_out, outp, N);
    logsoftmax64_kernel<<<(N + 7) / 8, 256>>>(outp, N);
}

// round 14
// speedup vs baseline: 1.5005x; 1.5005x over previous
#include <cuda_runtime.h>
#include <cuda_bf16.h>
#include <mma.h>
#include <math.h>
#include <cstdint>

using namespace nvcuda;

// ---------------- problem constants ----------------
#define HDIM 128                 // F_IN == H == 128
#define MAXN 50048               // 391 * 128, padded node count
#define MAXNNZ 700000
#define NFEAT_PAD (MAXN * HDIM)

// ---------------- device scratch (allocation-free) ----------------
__device__ float g_deg[MAXN];
__device__ float g_dinv[MAXN];
__device__ int   g_cnt[MAXN];
__device__ int   g_off[MAXN + 1];
__device__ int   g_fill[MAXN];
__device__ int   g_src[MAXNNZ];
__device__ float g_wc[MAXNNZ];
__device__ __nv_bfloat16 g_hb[NFEAT_PAD];   // bf16 inter-layer state (agg input)
__device__ float g_h0[NFEAT_PAD];
__device__ float g_ag[NFEAT_PAD];
__device__ int   g_bsum[64];
__device__ int   g_boff[65];

// ---------------- graph preprocessing ----------------
__global__ void init_kernel(float* deg, int* cnt, int n) {
    int i = blockIdx.x * blockDim.x + threadIdx.x;
    if (i < n) { deg[i] = 1.0f; cnt[i] = 1; }   // self-loop weight 1, self in-edge
}

__global__ void edge_count_kernel(const int* __restrict__ row, const int* __restrict__ col,
                                  const float* __restrict__ w, float* deg, int* cnt, int E) {
    int e = blockIdx.x * blockDim.x + threadIdx.x;
    if (e < E) {
        atomicAdd(&deg[row[e]], w[e]);
        atomicAdd(&cnt[col[e]], 1);
    }
}

__global__ void dinv_kernel(const float* __restrict__ deg, float* dinv, int n) {
    int i = blockIdx.x * blockDim.x + threadIdx.x;
    if (i < n) dinv[i] = rsqrtf(deg[i]);   // deg >= 1 always
}

// ---- multi-block exclusive scan: per-block scan -> scan of block sums -> fixup ----
__global__ void scan_block_kernel(const int* __restrict__ cnt, int* off, int n) {
    __shared__ int sm[1024];
    int i = blockIdx.x * 1024 + threadIdx.x;
    int v = (i < n) ? cnt[i] : 0;
    sm[threadIdx.x] = v;
    __syncthreads();
#pragma unroll
    for (int d = 1; d < 1024; d <<= 1) {
        int t = (threadIdx.x >= d) ? sm[threadIdx.x - d] : 0;
        __syncthreads();
        sm[threadIdx.x] += t;
        __syncthreads();
    }
    if (i < n) off[i] = sm[threadIdx.x] - v;     // exclusive within block
    if (threadIdx.x == 1023) g_bsum[blockIdx.x] = sm[1023];
}

__global__ void scan_bsums_kernel(int nb) {
    if (threadIdx.x == 0) {
        int acc = 0;
        for (int b = 0; b < nb; b++) { g_boff[b] = acc; acc += g_bsum[b]; }
        g_boff[nb] = acc;
    }
}

__global__ void scan_fixup_kernel(int* off, int* fill, int n, int nb) {
    int i = blockIdx.x * 1024 + threadIdx.x;
    if (i < n) {
        int o = off[i] + g_boff[blockIdx.x];
        off[i] = o; fill[i] = o;
    }
    if (i == 0) off[n] = g_boff[nb];
}

__global__ void fill_edges_kernel(const int* __restrict__ row, const int* __restrict__ col,
                                  const float* __restrict__ w, const float* __restrict__ dinv,
                                  int* fill, int* srcv, float* wcsc, int E) {
    int e = blockIdx.x * blockDim.x + threadIdx.x;
    if (e < E) {
        int r = row[e], c = col[e];
        int p = atomicAdd(&fill[c], 1);
        srcv[p] = r;
        wcsc[p] = dinv[r] * w[e] * dinv[c];
    }
}

__global__ void fill_self_kernel(const float* __restrict__ dinv, int* fill,
                                 int* srcv, float* wcsc, int n) {
    int i = blockIdx.x * blockDim.x + threadIdx.x;
    if (i < n) {
        int p = atomicAdd(&fill[i], 1);
        srcv[p] = i;
        wcsc[p] = dinv[i] * dinv[i];
    }
}

// zero padding rows [N, MAXN) of h0 and ag so guard-free GEMMs read zeros
// (g_hb padding rows are never written and never read meaningfully)
__global__ void pad_kernel(float* h0, float* ag, int startElem, int totalElem) {
    int i = blockIdx.x * blockDim.x + threadIdx.x + startElem;
    if (i < totalElem) { h0[i] = 0.0f; ag[i] = 0.0f; }
}

// ---------------- fp32 SGEMM tiles (input / output linears) ----------------
#define BM 128
#define BN 128
#define BK 8
#define TM 8
#define TN 8

// ---- input linear: h0(fp32) = hb(bf16) = relu(x @ w_in + b), guarded ----
__global__ void __launch_bounds__(256, 2)
gemm_in(const float* __restrict__ A, const float* __restrict__ W,
        const float* __restrict__ bias, __nv_bfloat16* __restrict__ hb,
        float* __restrict__ h0, int M) {
    __shared__ float As[BK][BM];
    __shared__ float Bs[BK][BN];
    const int tid = threadIdx.x;
    const int tx = tid & 15, ty = tid >> 4;
    const int m0 = blockIdx.x * BM;
    const int arow = tid >> 1, acol4 = (tid & 1) * 4;
    const int brow = tid >> 5, bcol4 = (tid & 31) * 4;

    float acc[TM][TN];
#pragma unroll
    for (int i = 0; i < TM; i++)
#pragma unroll
        for (int j = 0; j < TN; j++) acc[i][j] = 0.0f;

    for (int k0 = 0; k0 < HDIM; k0 += BK) {
        float4 av = make_float4(0.f, 0.f, 0.f, 0.f);
        int am = m0 + arow;
        if (am < M) av = *reinterpret_cast<const float4*>(A + (size_t)am * HDIM + k0 + acol4);
        As[acol4 + 0][arow] = av.x; As[acol4 + 1][arow] = av.y;
        As[acol4 + 2][arow] = av.z; As[acol4 + 3][arow] = av.w;

        float4 bv = *reinterpret_cast<const float4*>(W + (size_t)(k0 + brow) * HDIM + bcol4);
        Bs[brow][bcol4 + 0] = bv.x; Bs[brow][bcol4 + 1] = bv.y;
        Bs[brow][bcol4 + 2] = bv.z; Bs[brow][bcol4 + 3] = bv.w;
        __syncthreads();

#pragma unroll
        for (int kk = 0; kk < BK; kk++) {
            float ra[TM], rb[TN];
#pragma unroll
            for (int i = 0; i < TM; i++) ra[i] = As[kk][ty * TM + i];
#pragma unroll
            for (int j = 0; j < TN; j++) rb[j] = Bs[kk][tx * TN + j];
#pragma unroll
            for (int i = 0; i < TM; i++)
#pragma unroll
                for (int j = 0; j < TN; j++) acc[i][j] += ra[i] * rb[j];
        }
        __syncthreads();
    }

    float b0[TN];
#pragma unroll
    for (int j = 0; j < TN; j++) b0[j] = bias[tx * TN + j];

#pragma unroll
    for (int i = 0; i < TM; i++) {
        int m = m0 + ty * TM + i;
        if (m >= M) continue;
        float o[8];
#pragma unroll
        for (int j = 0; j < TN; j++) o[j] = fmaxf(acc[i][j] + b0[j], 0.0f);
        // fp32 h0
        float4* p2 = reinterpret_cast<float4*>(h0 + (size_t)m * HDIM + tx * TN);
        p2[0] = make_float4(o[0], o[1], o[2], o[3]);
        p2[1] = make_float4(o[4], o[5], o[6], o[7]);
        // bf16 h state
        union { __nv_bfloat162 p[4]; uint4 u; } pk;
#pragma unroll
        for (int q = 0; q < 4; q++)
            pk.p[q] = __halves2bfloat162(__float2bfloat16(o[q * 2]),
                                         __float2bfloat16(o[q * 2 + 1]));
        *reinterpret_cast<uint4*>(hb + (size_t)m * HDIM + tx * TN) = pk.u;
    }
}

// ---- output linear: out[M,64] = hb(bf16) @ w_out + b_out ----
__global__ void __launch_bounds__(256, 2)
gemm_out(const __nv_bfloat16* __restrict__ A, const float* __restrict__ W,
         const float* __restrict__ bias, float* __restrict__ out, int M) {
    __shared__ float As[BK][BM];
    __shared__ float Bs[BK][BN];
    const int tid = threadIdx.x;
    const int tx = tid & 15, ty = tid >> 4;
    const int m0 = blockIdx.x * BM;
    const int arow = tid >> 1, acol4 = (tid & 1) * 4;
    const int brow = tid >> 5, bcol4 = (tid & 31) * 4;
    const int Nn = 64;

    float acc[TM][TN];
#pragma unroll
    for (int i = 0; i < TM; i++)
#pragma unroll
        for (int j = 0; j < TN; j++) acc[i][j] = 0.0f;

    for (int k0 = 0; k0 < HDIM; k0 += BK) {
        // A tile from bf16 (padding rows read zeros; values beyond M unused anyway)
        uint2 v = *reinterpret_cast<const uint2*>(A + (size_t)(m0 + arow) * HDIM + k0 + acol4);
        float2 f01 = __bfloat1622float2(*reinterpret_cast<const __nv_bfloat162*>(&v.x));
        float2 f23 = __bfloat1622float2(*reinterpret_cast<const __nv_bfloat162*>(&v.y));
        As[acol4 + 0][arow] = f01.x; As[acol4 + 1][arow] = f01.y;
        As[acol4 + 2][arow] = f23.x; As[acol4 + 3][arow] = f23.y;

        float4 bv = make_float4(0.f, 0.f, 0.f, 0.f);
        if (bcol4 < Nn) bv = *reinterpret_cast<const float4*>(W + (size_t)(k0 + brow) * Nn + bcol4);
        Bs[brow][bcol4 + 0] = bv.x; Bs[brow][bcol4 + 1] = bv.y;
        Bs[brow][bcol4 + 2] = bv.z; Bs[brow][bcol4 + 3] = bv.w;
        __syncthreads();

#pragma unroll
        for (int kk = 0; kk < BK; kk++) {
            float ra[TM], rb[TN];
#pragma unroll
            for (int i = 0; i < TM; i++) ra[i] = As[kk][ty * TM + i];
#pragma unroll
            for (int j = 0; j < TN; j++) rb[j] = Bs[kk][tx * TN + j];
#pragma unroll
            for (int i = 0; i < TM; i++)
#pragma unroll
                for (int j = 0; j < TN; j++) acc[i][j] += ra[i] * rb[j];
        }
        __syncthreads();
    }

    if (tx < 8) {   // only columns < 64
        float b0[TN];
#pragma unroll
        for (int j = 0; j < TN; j++) b0[j] = bias[tx * TN + j];
#pragma unroll
        for (int i = 0; i < TM; i++) {
            int m = m0 + ty * TM + i;
            if (m >= M) continue;
            float4 o0, o1;
            o0.x = acc[i][0] + b0[0]; o0.y = acc[i][1] + b0[1];
            o0.z = acc[i][2] + b0[2]; o0.w = acc[i][3] + b0[3];
            o1.x = acc[i][4] + b0[4]; o1.y = acc[i][5] + b0[5];
            o1.z = acc[i][6] + b0[6]; o1.w = acc[i][7] + b0[7];
            float4* p = reinterpret_cast<float4*>(out + (size_t)m * Nn + tx * TN);
            p[0] = o0; p[1] = o1;
        }
    }
}

// ---------------- tf32 tensor-core fused layer GEMM (R10-proven mainloop) ----------
// hb_out(bf16) = relu( cs*ag + ci*h0 + beta*( ag@W1 + h0@W2 ) )   (padded M)
// CTA: 128x128 tile, 8 warps 4x2; warp tile 32x64 = 2x4 wmma 16x16 frags.
// Accumulators initialized from fp32 residual; beta folded into B at smem load;
// epilogue stages each fragment in warp-private smem and emits bf16.
#define SA_LD 24     // A tile leading dim (16 k + 8 pad)
#define SB_LD 136    // B tile leading dim (128 n + 8 pad)
#define SLDM 20      // epilogue staging leading dim (multiple of 4)

__global__ void __launch_bounds__(256)
gemm_layer_tc(const float* __restrict__ ag, const float* __restrict__ h0,
              const float* __restrict__ W1, const float* __restrict__ W2,
              __nv_bfloat16* __restrict__ hb, float cs, float ci, float beta) {
    __shared__ float sA[128 * SA_LD];   // 3072 floats
    __shared__ float sB[16 * SB_LD];    // 2176 floats

    const int tid = threadIdx.x;
    const int wid = tid >> 5;
    const int lane = tid & 31;
    const int warp_m = wid >> 1;          // 0..3
    const int warp_n = wid & 1;           // 0..1
    const int m0 = blockIdx.x * 128;

    // ---- init accumulators with the exact-fp32 residual: cs*ag + ci*h0 ----
    wmma::fragment<wmma::accumulator, 16, 16, 8, float> C[2][4];
#pragma unroll
    for (int mi = 0; mi < 2; mi++) {
        const size_t rbase = (size_t)(m0 + warp_m * 32 + mi * 16) * HDIM;
#pragma unroll
        for (int ni = 0; ni < 4; ni++) {
            const int coff = warp_n * 64 + ni * 16;
            wmma::fragment<wmma::accumulator, 16, 16, 8, float> Ra, Rb;
            wmma::load_matrix_sync(Ra, ag + rbase + coff, HDIM, wmma::mem_row_major);
            wmma::load_matrix_sync(Rb, h0 + rbase + coff, HDIM, wmma::mem_row_major);
#pragma unroll
            for (int t = 0; t < Ra.num_elements; t++)
                C[mi][ni].x[t] = cs * Ra.x[t] + ci * Rb.x[t];
        }
    }

    // tile-load thread mapping
    const int a_row = tid >> 1, a_seg = (tid & 1) * 8;        // A: 2 thr/row, 8 floats each
    const int b_row = tid >> 4, b_col = (tid & 15) * 8;       // B: 16 thr/row, 8 floats each

#pragma unroll 1
    for (int half = 0; half < 2; half++) {
        const float* Abase = (half ? h0 : ag) + (size_t)m0 * HDIM;
        const float* Wbase = half ? W2 : W1;
#pragma unroll 1
        for (int k0 = 0; k0 < HDIM; k0 += 16) {
            __syncthreads();
            // load A tile: rows 0..127, k columns k0..k0+15
            {
                const float4* p = reinterpret_cast<const float4*>(Abase + (size_t)a_row * HDIM + k0 + a_seg);
                float4 v0 = p[0], v1 = p[1];
                float* d = sA + a_row * SA_LD + a_seg;
                d[0] = v0.x; d[1] = v0.y; d[2] = v0.z; d[3] = v0.w;
                d[4] = v1.x; d[5] = v1.y; d[6] = v1.z; d[7] = v1.w;
            }
            // load B tile scaled by beta: W rows k0..k0+15, all 128 columns
            {
                const float4* p = reinterpret_cast<const float4*>(Wbase + (size_t)(k0 + b_row) * HDIM + b_col);
                float4 v0 = p[0], v1 = p[1];
                float* d = sB + b_row * SB_LD + b_col;
                d[0] = beta * v0.x; d[1] = beta * v0.y; d[2] = beta * v0.z; d[3] = beta * v0.w;
                d[4] = beta * v1.x; d[5] = beta * v1.y; d[6] = beta * v1.z; d[7] = beta * v1.w;
            }
            __syncthreads();

#pragma unroll
            for (int kk = 0; kk < 16; kk += 8) {
                wmma::fragment<wmma::matrix_a, 16, 16, 8, wmma::precision::tf32, wmma::row_major> a[2];
#pragma unroll
                for (int mi = 0; mi < 2; mi++) {
                    wmma::load_matrix_sync(a[mi], sA + (warp_m * 32 + mi * 16) * SA_LD + kk, SA_LD);
#pragma unroll
                    for (int t = 0; t < a[mi].num_elements; t++)
                        a[mi].x[t] = wmma::__float_to_tf32(a[mi].x[t]);
                }
#pragma unroll
                for (int ni = 0; ni < 4; ni++) {
                    wmma::fragment<wmma::matrix_b, 16, 16, 8, wmma::precision::tf32, wmma::row_major> b;
                    wmma::load_matrix_sync(b, sB + kk * SB_LD + warp_n * 64 + ni * 16, SB_LD);
#pragma unroll
                    for (int t = 0; t < b.num_elements; t++)
                        b.x[t] = wmma::__float_to_tf32(b.x[t]);
#pragma unroll
                    for (int mi = 0; mi < 2; mi++)
                        wmma::mma_sync(C[mi][ni], a[mi], b, C[mi][ni]);
                }
            }
        }
    }

    // ---- epilogue: stage each frag in warp-private smem, relu, emit bf16 ----
    __syncthreads();                       // all warps done reading sA/sB
    float* stage = sA + wid * (16 * SLDM); // 320 floats per warp, 8*320=2560 <= 3072
    const int r = lane >> 1;
    const int cseg = (lane & 1) * 8;
#pragma unroll
    for (int mi = 0; mi < 2; mi++) {
#pragma unroll
        for (int ni = 0; ni < 4; ni++) {
            wmma::store_matrix_sync(stage, C[mi][ni], SLDM, wmma::mem_row_major);
            __syncwarp();
            const float* sp = stage + r * SLDM + cseg;
            union { __nv_bfloat162 p[4]; uint4 u; } pk;
#pragma unroll
            for (int q = 0; q < 4; q++) {
                float f0 = fmaxf(sp[q * 2 + 0], 0.0f);
                float f1 = fmaxf(sp[q * 2 + 1], 0.0f);
                pk.p[q] = __halves2bfloat162(__float2bfloat16(f0), __float2bfloat16(f1));
            }
            size_t row = (size_t)(m0 + warp_m * 32 + mi * 16 + r);
            int col = warp_n * 64 + ni * 16 + cseg;
            *reinterpret_cast<uint4*>(hb + row * HDIM + col) = pk.u;
            __syncwarp();
        }
    }
}

// ---------------- atomic-free CSC aggregation (bf16 gather, fp32 accumulate) ----
// ag[c,:] = sum_j wc[j] * hb[src[j],:]
__global__ void agg_kernel(const __nv_bfloat16* __restrict__ hb,
                           const int* __restrict__ off, const int* __restrict__ src,
                           const float* __restrict__ wc, float* __restrict__ ag, int n) {
    int node = (blockIdx.x * blockDim.x + threadIdx.x) >> 5;
    int lane = threadIdx.x & 31;
    if (node >= n) return;
    int s = off[node], e = off[node + 1];
    const uint2* H2 = reinterpret_cast<const uint2*>(hb);   // 32 uint2 per row
    float4 acc = make_float4(0.f, 0.f, 0.f, 0.f);
    int j = s;
    for (; j + 1 < e; j += 2) {
        int s0 = src[j], s1 = src[j + 1];
        float w0 = wc[j], w1 = wc[j + 1];
        uint2 v0 = H2[(size_t)s0 * 32 + lane];
        uint2 v1 = H2[(size_t)s1 * 32 + lane];
        float2 a01 = __bfloat1622float2(*reinterpret_cast<const __nv_bfloat162*>(&v0.x));
        float2 a23 = __bfloat1622float2(*reinterpret_cast<const __nv_bfloat162*>(&v0.y));
        float2 b01 = __bfloat1622float2(*reinterpret_cast<const __nv_bfloat162*>(&v1.x));
        float2 b23 = __bfloat1622float2(*reinterpret_cast<const __nv_bfloat162*>(&v1.y));
        acc.x += w0 * a01.x; acc.y += w0 * a01.y; acc.z += w0 * a23.x; acc.w += w0 * a23.y;
        acc.x += w1 * b01.x; acc.y += w1 * b01.y; acc.z += w1 * b23.x; acc.w += w1 * b23.y;
    }
    if (j < e) {
        float w0 = wc[j];
        uint2 v0 = H2[(size_t)src[j] * 32 + lane];
        float2 a01 = __bfloat1622float2(*reinterpret_cast<const __nv_bfloat162*>(&v0.x));
        float2 a23 = __bfloat1622float2(*reinterpret_cast<const __nv_bfloat162*>(&v0.y));
        acc.x += w0 * a01.x; acc.y += w0 * a01.y; acc.z += w0 * a23.x; acc.w += w0 * a23.y;
    }
    reinterpret_cast<float4*>(ag)[(size_t)node * 32 + lane] = acc;
}

// ---------------- log_softmax over 64 classes, in place ----------------
__global__ void logsoftmax64_kernel(float* __restrict__ out, int n) {
    int row = blockIdx.x * 8 + (threadIdx.x >> 5);
    int lane = threadIdx.x & 31;
    if (row >= n) return;
    float* p = out + (size_t)row * 64;
    float a = p[lane], b = p[lane + 32];
    float mx = fmaxf(a, b);
#pragma unroll
    for (int d = 16; d; d >>= 1) mx = fmaxf(mx, __shfl_xor_sync(0xFFFFFFFFu, mx, d));
    float s = __expf(a - mx) + __expf(b - mx);
#pragma unroll
    for (int d = 16; d; d >>= 1) s += __shfl_xor_sync(0xFFFFFFFFu, s, d);
    float lse = mx + __logf(s);
    p[lane] = a - lse;
    p[lane + 32] = b - lse;
}

// ---------------- launch ----------------
extern "C" void kernel_launch(void* const* d_in, const int* in_sizes, int n_in,
                              void* d_out, int out_size) {
    const float* x     = (const float*)d_in[0];
    const int*   ei    = (const int*)  d_in[1];
    const float* ew    = (const float*)d_in[2];
    const float* w_in  = (const float*)d_in[3];
    const float* b_in  = (const float*)d_in[4];
    const float* ws1   = (const float*)d_in[5];
    const float* ws2   = (const float*)d_in[6];
    const float* w_out = (const float*)d_in[7];
    const float* b_out = (const float*)d_in[8];

    const int N = in_sizes[0] / HDIM;            // 50000
    const int E = in_sizes[2];                   // 640000
    const int L = in_sizes[5] / (HDIM * HDIM);   // 16
    const float ALPHA = 0.1f;
    const double LAMDA = 0.5;

    const int* erow = ei;
    const int* ecol = ei + E;

    float *deg, *dinv, *wc, *h0, *ag;
    __nv_bfloat16* hb;
    int *cnt, *off, *fill, *src;
    cudaGetSymbolAddress((void**)&deg,  g_deg);
    cudaGetSymbolAddress((void**)&dinv, g_dinv);
    cudaGetSymbolAddress((void**)&cnt,  g_cnt);
    cudaGetSymbolAddress((void**)&off,  g_off);
    cudaGetSymbolAddress((void**)&fill, g_fill);
    cudaGetSymbolAddress((void**)&src,  g_src);
    cudaGetSymbolAddress((void**)&wc,   g_wc);
    cudaGetSymbolAddress((void**)&hb,   g_hb);
    cudaGetSymbolAddress((void**)&h0,   g_h0);
    cudaGetSymbolAddress((void**)&ag,   g_ag);

    const int TB = 256;
    const int gN = (N + TB - 1) / TB;
    const int gE = (E + TB - 1) / TB;
    const int nb = (N + 1023) / 1024;            // 49 scan blocks

    // ---- graph normalization + CSC build ----
    init_kernel<<<gN, TB>>>(deg, cnt, N);
    edge_count_kernel<<<gE, TB>>>(erow, ecol, ew, deg, cnt, E);
    dinv_kernel<<<gN, TB>>>(deg, dinv, N);
    scan_block_kernel<<<nb, 1024>>>(cnt, off, N);
    scan_bsums_kernel<<<1, 32>>>(nb);
    scan_fixup_kernel<<<nb, 1024>>>(off, fill, N, nb);
    fill_edges_kernel<<<gE, TB>>>(erow, ecol, ew, dinv, fill, src, wc, E);
    fill_self_kernel<<<gN, TB>>>(dinv, fill, src, wc, N);

    // zero padding rows of h0/ag
    {
        int startElem = N * HDIM;
        int padElems = NFEAT_PAD - startElem;
        pad_kernel<<<(padElems + TB - 1) / TB, TB>>>(h0, ag, startElem, NFEAT_PAD);
    }

    const int gGemm = MAXN / BM;   // 391, covers padded rows

    // ---- input linear + relu; hb (bf16) and h0 (fp32) ----
    gemm_in<<<gGemm, 256>>>(x, w_in, b_in, hb, h0, N);

    // ---- GCNII layers: ag = A_hat@hb, then fused tf32 K=256 GEMM -> hb ----
    for (int i = 0; i < L; i++) {
        float beta = (float)log(LAMDA / (double)(i + 1) + 1.0);
        float cs = (1.0f - beta) * (1.0f - ALPHA);
        float ci = (1.0f - beta) * ALPHA;
        agg_kernel<<<(N * 32 + 255) / 256, 256>>>(hb, off, src, wc, ag, N);
        gemm_layer_tc<<<gGemm, 256>>>(ag, h0,
                                      ws1 + (size_t)i * HDIM * HDIM,
                                      ws2 + (size_t)i * HDIM * HDIM,
                                      hb, cs, ci, beta);
    }

    // ---- output linear + log_softmax ----
    float* outp = (float*)d_out;
    gemm_out<<<gGemm, 256>>>(hb, w_out, b_out, outp, N);
    logsoftmax64_kernel<<<(N + 7) / 8, 256>>>(outp, N);
}

// round 16
// speedup vs baseline: 2.1325x; 1.4212x over previous
#include <cuda_runtime.h>
#include <cuda_bf16.h>
#include <mma.h>
#include <math.h>
#include <cstdint>

using namespace nvcuda;

// ---------------- problem constants ----------------
#define HDIM 128                 // F_IN == H == 128
#define MAXN 50048               // 391 * 128, padded node count
#define MAXNNZ 700000
#define NFEAT_PAD (MAXN * HDIM)

// ---------------- device scratch (allocation-free) ----------------
__device__ float g_deg[MAXN];
__device__ float g_dinv[MAXN];
__device__ int   g_cnt[MAXN];
__device__ int   g_off[MAXN + 1];
__device__ int   g_fill[MAXN];
__device__ int   g_src[MAXNNZ];
__device__ float g_wc[MAXNNZ];
__device__ __nv_bfloat16 g_hb[NFEAT_PAD];   // bf16 inter-layer state (agg input)
__device__ float g_h0[NFEAT_PAD];
__device__ float g_ag[NFEAT_PAD];
__device__ int   g_bsum[64];
__device__ int   g_boff[65];

// ---------------- graph preprocessing ----------------
__global__ void init_kernel(float* deg, int* cnt, int n) {
    int i = blockIdx.x * blockDim.x + threadIdx.x;
    if (i < n) { deg[i] = 1.0f; cnt[i] = 1; }   // self-loop weight 1, self in-edge
}

__global__ void edge_count_kernel(const int* __restrict__ row, const int* __restrict__ col,
                                  const float* __restrict__ w, float* deg, int* cnt, int E) {
    int e = blockIdx.x * blockDim.x + threadIdx.x;
    if (e < E) {
        atomicAdd(&deg[row[e]], w[e]);
        atomicAdd(&cnt[col[e]], 1);
    }
}

__global__ void dinv_kernel(const float* __restrict__ deg, float* dinv, int n) {
    int i = blockIdx.x * blockDim.x + threadIdx.x;
    if (i < n) dinv[i] = rsqrtf(deg[i]);   // deg >= 1 always
}

// ---- multi-block exclusive scan: per-block scan -> scan of block sums -> fixup ----
__global__ void scan_block_kernel(const int* __restrict__ cnt, int* off, int n) {
    __shared__ int sm[1024];
    int i = blockIdx.x * 1024 + threadIdx.x;
    int v = (i < n) ? cnt[i] : 0;
    sm[threadIdx.x] = v;
    __syncthreads();
#pragma unroll
    for (int d = 1; d < 1024; d <<= 1) {
        int t = (threadIdx.x >= d) ? sm[threadIdx.x - d] : 0;
        __syncthreads();
        sm[threadIdx.x] += t;
        __syncthreads();
    }
    if (i < n) off[i] = sm[threadIdx.x] - v;     // exclusive within block
    if (threadIdx.x == 1023) g_bsum[blockIdx.x] = sm[1023];
}

__global__ void scan_bsums_kernel(int nb) {
    if (threadIdx.x == 0) {
        int acc = 0;
        for (int b = 0; b < nb; b++) { g_boff[b] = acc; acc += g_bsum[b]; }
        g_boff[nb] = acc;
    }
}

__global__ void scan_fixup_kernel(int* off, int* fill, int n, int nb) {
    int i = blockIdx.x * 1024 + threadIdx.x;
    if (i < n) {
        int o = off[i] + g_boff[blockIdx.x];
        off[i] = o; fill[i] = o;
    }
    if (i == 0) off[n] = g_boff[nb];
}

__global__ void fill_edges_kernel(const int* __restrict__ row, const int* __restrict__ col,
                                  const float* __restrict__ w, const float* __restrict__ dinv,
                                  int* fill, int* srcv, float* wcsc, int E) {
    int e = blockIdx.x * blockDim.x + threadIdx.x;
    if (e < E) {
        int r = row[e], c = col[e];
        int p = atomicAdd(&fill[c], 1);
        srcv[p] = r;
        wcsc[p] = dinv[r] * w[e] * dinv[c];
    }
}

__global__ void fill_self_kernel(const float* __restrict__ dinv, int* fill,
                                 int* srcv, float* wcsc, int n) {
    int i = blockIdx.x * blockDim.x + threadIdx.x;
    if (i < n) {
        int p = atomicAdd(&fill[i], 1);
        srcv[p] = i;
        wcsc[p] = dinv[i] * dinv[i];
    }
}

// zero padding rows [N, MAXN) of h0 and ag so guard-free GEMMs read zeros
__global__ void pad_kernel(float* h0, float* ag, int startElem, int totalElem) {
    int i = blockIdx.x * blockDim.x + threadIdx.x + startElem;
    if (i < totalElem) { h0[i] = 0.0f; ag[i] = 0.0f; }
}

// ---------------- fp32 SGEMM tiles (input / output linears) ----------------
#define BM 128
#define BN 128
#define BK 8
#define TM 8
#define TN 8

// ---- input linear: h0(fp32) = hb(bf16) = relu(x @ w_in + b), guarded ----
__global__ void __launch_bounds__(256, 2)
gemm_in(const float* __restrict__ A, const float* __restrict__ W,
        const float* __restrict__ bias, __nv_bfloat16* __restrict__ hb,
        float* __restrict__ h0, int M) {
    __shared__ float As[BK][BM];
    __shared__ float Bs[BK][BN];
    const int tid = threadIdx.x;
    const int tx = tid & 15, ty = tid >> 4;
    const int m0 = blockIdx.x * BM;
    const int arow = tid >> 1, acol4 = (tid & 1) * 4;
    const int brow = tid >> 5, bcol4 = (tid & 31) * 4;

    float acc[TM][TN];
#pragma unroll
    for (int i = 0; i < TM; i++)
#pragma unroll
        for (int j = 0; j < TN; j++) acc[i][j] = 0.0f;

    for (int k0 = 0; k0 < HDIM; k0 += BK) {
        float4 av = make_float4(0.f, 0.f, 0.f, 0.f);
        int am = m0 + arow;
        if (am < M) av = *reinterpret_cast<const float4*>(A + (size_t)am * HDIM + k0 + acol4);
        As[acol4 + 0][arow] = av.x; As[acol4 + 1][arow] = av.y;
        As[acol4 + 2][arow] = av.z; As[acol4 + 3][arow] = av.w;

        float4 bv = *reinterpret_cast<const float4*>(W + (size_t)(k0 + brow) * HDIM + bcol4);
        Bs[brow][bcol4 + 0] = bv.x; Bs[brow][bcol4 + 1] = bv.y;
        Bs[brow][bcol4 + 2] = bv.z; Bs[brow][bcol4 + 3] = bv.w;
        __syncthreads();

#pragma unroll
        for (int kk = 0; kk < BK; kk++) {
            float ra[TM], rb[TN];
#pragma unroll
            for (int i = 0; i < TM; i++) ra[i] = As[kk][ty * TM + i];
#pragma unroll
            for (int j = 0; j < TN; j++) rb[j] = Bs[kk][tx * TN + j];
#pragma unroll
            for (int i = 0; i < TM; i++)
#pragma unroll
                for (int j = 0; j < TN; j++) acc[i][j] += ra[i] * rb[j];
        }
        __syncthreads();
    }

    float b0[TN];
#pragma unroll
    for (int j = 0; j < TN; j++) b0[j] = bias[tx * TN + j];

#pragma unroll
    for (int i = 0; i < TM; i++) {
        int m = m0 + ty * TM + i;
        if (m >= M) continue;
        float o[8];
#pragma unroll
        for (int j = 0; j < TN; j++) o[j] = fmaxf(acc[i][j] + b0[j], 0.0f);
        float4* p2 = reinterpret_cast<float4*>(h0 + (size_t)m * HDIM + tx * TN);
        p2[0] = make_float4(o[0], o[1], o[2], o[3]);
        p2[1] = make_float4(o[4], o[5], o[6], o[7]);
        union { __nv_bfloat162 p[4]; uint4 u; } pk;
#pragma unroll
        for (int q = 0; q < 4; q++)
            pk.p[q] = __halves2bfloat162(__float2bfloat16(o[q * 2]),
                                         __float2bfloat16(o[q * 2 + 1]));
        *reinterpret_cast<uint4*>(hb + (size_t)m * HDIM + tx * TN) = pk.u;
    }
}

// ---- output linear: out[M,64] = hb(bf16) @ w_out + b_out ----
__global__ void __launch_bounds__(256, 2)
gemm_out(const __nv_bfloat16* __restrict__ A, const float* __restrict__ W,
         const float* __restrict__ bias, float* __restrict__ out, int M) {
    __shared__ float As[BK][BM];
    __shared__ float Bs[BK][BN];
    const int tid = threadIdx.x;
    const int tx = tid & 15, ty = tid >> 4;
    const int m0 = blockIdx.x * BM;
    const int arow = tid >> 1, acol4 = (tid & 1) * 4;
    const int brow = tid >> 5, bcol4 = (tid & 31) * 4;
    const int Nn = 64;

    float acc[TM][TN];
#pragma unroll
    for (int i = 0; i < TM; i++)
#pragma unroll
        for (int j = 0; j < TN; j++) acc[i][j] = 0.0f;

    for (int k0 = 0; k0 < HDIM; k0 += BK) {
        uint2 v = *reinterpret_cast<const uint2*>(A + (size_t)(m0 + arow) * HDIM + k0 + acol4);
        float2 f01 = __bfloat1622float2(*reinterpret_cast<const __nv_bfloat162*>(&v.x));
        float2 f23 = __bfloat1622float2(*reinterpret_cast<const __nv_bfloat162*>(&v.y));
        As[acol4 + 0][arow] = f01.x; As[acol4 + 1][arow] = f01.y;
        As[acol4 + 2][arow] = f23.x; As[acol4 + 3][arow] = f23.y;

        float4 bv = make_float4(0.f, 0.f, 0.f, 0.f);
        if (bcol4 < Nn) bv = *reinterpret_cast<const float4*>(W + (size_t)(k0 + brow) * Nn + bcol4);
        Bs[brow][bcol4 + 0] = bv.x; Bs[brow][bcol4 + 1] = bv.y;
        Bs[brow][bcol4 + 2] = bv.z; Bs[brow][bcol4 + 3] = bv.w;
        __syncthreads();

#pragma unroll
        for (int kk = 0; kk < BK; kk++) {
            float ra[TM], rb[TN];
#pragma unroll
            for (int i = 0; i < TM; i++) ra[i] = As[kk][ty * TM + i];
#pragma unroll
            for (int j = 0; j < TN; j++) rb[j] = Bs[kk][tx * TN + j];
#pragma unroll
            for (int i = 0; i < TM; i++)
#pragma unroll
                for (int j = 0; j < TN; j++) acc[i][j] += ra[i] * rb[j];
        }
        __syncthreads();
    }

    if (tx < 8) {   // only columns < 64
        float b0[TN];
#pragma unroll
        for (int j = 0; j < TN; j++) b0[j] = bias[tx * TN + j];
#pragma unroll
        for (int i = 0; i < TM; i++) {
            int m = m0 + ty * TM + i;
            if (m >= M) continue;
            float4 o0, o1;
            o0.x = acc[i][0] + b0[0]; o0.y = acc[i][1] + b0[1];
            o0.z = acc[i][2] + b0[2]; o0.w = acc[i][3] + b0[3];
            o1.x = acc[i][4] + b0[4]; o1.y = acc[i][5] + b0[5];
            o1.z = acc[i][6] + b0[6]; o1.w = acc[i][7] + b0[7];
            float4* p = reinterpret_cast<float4*>(out + (size_t)m * Nn + tx * TN);
            p[0] = o0; p[1] = o1;
        }
    }
}

// ---------------- bf16 tensor-core fused layer GEMM (register-prefetch pipeline) ----
// hb_out(bf16) = relu( cs*ag + ci*h0 + beta*( ag@W1 + h0@W2 ) )   (padded M)
// CTA: 128x128 tile, 8 warps 4x2; warp tile 32x64 = 2x4 wmma m16n16k16 frags.
// Residual init fp32; beta folded into bf16 B tile; A/B operands bf16 (k16 mma).
// Two-sync register pipeline: STS tile kt, issue LDGs for kt+1, sync, compute kt.
// Shared: sA 128x24 bf16 (6144 B) + sB 16x136 bf16 (4352 B) = 10496 B,
// reused as 8x(16x20) fp32 epilogue staging (10240 B).
#define TCA_LD 24    // bf16 elems per A row (16 + 8 pad), 48 B (mult of 16)
#define TCB_LD 136   // bf16 elems per B row (128 + 8 pad), 272 B (mult of 16)
#define SLDM 20      // epilogue staging leading dim (floats)

__global__ void __launch_bounds__(256)
gemm_layer_tc(const float* __restrict__ ag, const float* __restrict__ h0,
              const float* __restrict__ W1, const float* __restrict__ W2,
              __nv_bfloat16* __restrict__ hb, float cs, float ci, float beta) {
    __shared__ __align__(16) unsigned char smraw[(128 * TCA_LD + 16 * TCB_LD) * 2];
    __nv_bfloat16* sA = reinterpret_cast<__nv_bfloat16*>(smraw);
    __nv_bfloat16* sB = reinterpret_cast<__nv_bfloat16*>(smraw) + 128 * TCA_LD;

    const int tid = threadIdx.x;
    const int wid = tid >> 5;
    const int lane = tid & 31;
    const int warp_m = wid >> 1;          // 0..3
    const int warp_n = wid & 1;           // 0..1
    const int m0 = blockIdx.x * 128;

    // ---- init accumulators with the exact-fp32 residual: cs*ag + ci*h0 ----
    wmma::fragment<wmma::accumulator, 16, 16, 16, float> C[2][4];
#pragma unroll
    for (int mi = 0; mi < 2; mi++) {
        const size_t rbase = (size_t)(m0 + warp_m * 32 + mi * 16) * HDIM;
#pragma unroll
        for (int ni = 0; ni < 4; ni++) {
            const int coff = warp_n * 64 + ni * 16;
            wmma::fragment<wmma::accumulator, 16, 16, 16, float> Ra, Rb;
            wmma::load_matrix_sync(Ra, ag + rbase + coff, HDIM, wmma::mem_row_major);
            wmma::load_matrix_sync(Rb, h0 + rbase + coff, HDIM, wmma::mem_row_major);
#pragma unroll
            for (int t = 0; t < Ra.num_elements; t++)
                C[mi][ni].x[t] = cs * Ra.x[t] + ci * Rb.x[t];
        }
    }

    // tile-load thread mapping
    const int a_row = tid >> 1, a_seg = (tid & 1) * 8;        // A: 2 thr/row, 8 floats
    const int b_row = tid >> 4, b_col = (tid & 15) * 8;       // B: 16 thr/row, 8 floats

    float ar[8], br[8];
    // prologue: load k-tile 0 (half 0: A=ag, W=W1) into registers
    {
        const float* Asrc = ag + (size_t)(m0 + a_row) * HDIM + a_seg;
        float4 v0 = reinterpret_cast<const float4*>(Asrc)[0];
        float4 v1 = reinterpret_cast<const float4*>(Asrc)[1];
        ar[0] = v0.x; ar[1] = v0.y; ar[2] = v0.z; ar[3] = v0.w;
        ar[4] = v1.x; ar[5] = v1.y; ar[6] = v1.z; ar[7] = v1.w;
        const float* Bsrc = W1 + (size_t)b_row * HDIM + b_col;
        float4 w0 = reinterpret_cast<const float4*>(Bsrc)[0];
        float4 w1 = reinterpret_cast<const float4*>(Bsrc)[1];
        br[0] = w0.x; br[1] = w0.y; br[2] = w0.z; br[3] = w0.w;
        br[4] = w1.x; br[5] = w1.y; br[6] = w1.z; br[7] = w1.w;
    }

#pragma unroll 1
    for (int kt = 0; kt < 16; kt++) {
        __syncthreads();   // previous tile's consumers done with smem
        // STS: convert regs -> bf16 smem (beta folded into B)
        {
            union { __nv_bfloat162 p[4]; uint4 u; } pa;
#pragma unroll
            for (int q = 0; q < 4; q++)
                pa.p[q] = __halves2bfloat162(__float2bfloat16(ar[q * 2]),
                                             __float2bfloat16(ar[q * 2 + 1]));
            *reinterpret_cast<uint4*>(sA + a_row * TCA_LD + a_seg) = pa.u;
            union { __nv_bfloat162 p[4]; uint4 u; } pb;
#pragma unroll
            for (int q = 0; q < 4; q++)
                pb.p[q] = __halves2bfloat162(__float2bfloat16(beta * br[q * 2]),
                                             __float2bfloat16(beta * br[q * 2 + 1]));
            *reinterpret_cast<uint4*>(sB + b_row * TCB_LD + b_col) = pb.u;
        }
        // prefetch k-tile kt+1 into registers (hides under compute below)
        if (kt + 1 < 16) {
            int nk = kt + 1;
            int half = nk >> 3;
            int k0 = (nk & 7) * 16;
            const float* Abase = half ? h0 : ag;
            const float* Wbase = half ? W2 : W1;
            const float* Asrc = Abase + (size_t)(m0 + a_row) * HDIM + k0 + a_seg;
            float4 v0 = reinterpret_cast<const float4*>(Asrc)[0];
            float4 v1 = reinterpret_cast<const float4*>(Asrc)[1];
            ar[0] = v0.x; ar[1] = v0.y; ar[2] = v0.z; ar[3] = v0.w;
            ar[4] = v1.x; ar[5] = v1.y; ar[6] = v1.z; ar[7] = v1.w;
            const float* Bsrc = Wbase + (size_t)(k0 + b_row) * HDIM + b_col;
            float4 w0 = reinterpret_cast<const float4*>(Bsrc)[0];
            float4 w1 = reinterpret_cast<const float4*>(Bsrc)[1];
            br[0] = w0.x; br[1] = w0.y; br[2] = w0.z; br[3] = w0.w;
            br[4] = w1.x; br[5] = w1.y; br[6] = w1.z; br[7] = w1.w;
        }
        __syncthreads();   // smem tile kt ready

        // compute tile kt: one k16 mma per (mi, ni)
        wmma::fragment<wmma::matrix_a, 16, 16, 16, __nv_bfloat16, wmma::row_major> a[2];
#pragma unroll
        for (int mi = 0; mi < 2; mi++)
            wmma::load_matrix_sync(a[mi], sA + (warp_m * 32 + mi * 16) * TCA_LD, TCA_LD);
#pragma unroll
        for (int ni = 0; ni < 4; ni++) {
            wmma::fragment<wmma::matrix_b, 16, 16, 16, __nv_bfloat16, wmma::row_major> b;
            wmma::load_matrix_sync(b, sB + warp_n * 64 + ni * 16, TCB_LD);
#pragma unroll
            for (int mi = 0; mi < 2; mi++)
                wmma::mma_sync(C[mi][ni], a[mi], b, C[mi][ni]);
        }
    }

    // ---- epilogue: stage each frag in warp-private smem, relu, emit bf16 ----
    __syncthreads();                       // all warps done reading sA/sB
    float* stage = reinterpret_cast<float*>(smraw) + wid * (16 * SLDM);
    const int r = lane >> 1;
    const int cseg = (lane & 1) * 8;
#pragma unroll
    for (int mi = 0; mi < 2; mi++) {
#pragma unroll
        for (int ni = 0; ni < 4; ni++) {
            wmma::store_matrix_sync(stage, C[mi][ni], SLDM, wmma::mem_row_major);
            __syncwarp();
            const float* sp = stage + r * SLDM + cseg;
            union { __nv_bfloat162 p[4]; uint4 u; } pk;
#pragma unroll
            for (int q = 0; q < 4; q++) {
                float f0 = fmaxf(sp[q * 2 + 0], 0.0f);
                float f1 = fmaxf(sp[q * 2 + 1], 0.0f);
                pk.p[q] = __halves2bfloat162(__float2bfloat16(f0), __float2bfloat16(f1));
            }
            size_t row = (size_t)(m0 + warp_m * 32 + mi * 16 + r);
            int col = warp_n * 64 + ni * 16 + cseg;
            *reinterpret_cast<uint4*>(hb + row * HDIM + col) = pk.u;
            __syncwarp();
        }
    }
}

// ---------------- atomic-free CSC aggregation (bf16 gather, fp32 accumulate) ----
// ag[c,:] = sum_j wc[j] * hb[src[j],:]
__global__ void agg_kernel(const __nv_bfloat16* __restrict__ hb,
                           const int* __restrict__ off, const int* __restrict__ src,
                           const float* __restrict__ wc, float* __restrict__ ag, int n) {
    int node = (blockIdx.x * blockDim.x + threadIdx.x) >> 5;
    int lane = threadIdx.x & 31;
    if (node >= n) return;
    int s = off[node], e = off[node + 1];
    const uint2* H2 = reinterpret_cast<const uint2*>(hb);   // 32 uint2 per row
    float4 acc = make_float4(0.f, 0.f, 0.f, 0.f);
    int j = s;
    for (; j + 1 < e; j += 2) {
        int s0 = src[j], s1 = src[j + 1];
        float w0 = wc[j], w1 = wc[j + 1];
        uint2 v0 = H2[(size_t)s0 * 32 + lane];
        uint2 v1 = H2[(size_t)s1 * 32 + lane];
        float2 a01 = __bfloat1622float2(*reinterpret_cast<const __nv_bfloat162*>(&v0.x));
        float2 a23 = __bfloat1622float2(*reinterpret_cast<const __nv_bfloat162*>(&v0.y));
        float2 b01 = __bfloat1622float2(*reinterpret_cast<const __nv_bfloat162*>(&v1.x));
        float2 b23 = __bfloat1622float2(*reinterpret_cast<const __nv_bfloat162*>(&v1.y));
        acc.x += w0 * a01.x; acc.y += w0 * a01.y; acc.z += w0 * a23.x; acc.w += w0 * a23.y;
        acc.x += w1 * b01.x; acc.y += w1 * b01.y; acc.z += w1 * b23.x; acc.w += w1 * b23.y;
    }
    if (j < e) {
        float w0 = wc[j];
        uint2 v0 = H2[(size_t)src[j] * 32 + lane];
        float2 a01 = __bfloat1622float2(*reinterpret_cast<const __nv_bfloat162*>(&v0.x));
        float2 a23 = __bfloat1622float2(*reinterpret_cast<const __nv_bfloat162*>(&v0.y));
        acc.x += w0 * a01.x; acc.y += w0 * a01.y; acc.z += w0 * a23.x; acc.w += w0 * a23.y;
    }
    reinterpret_cast<float4*>(ag)[(size_t)node * 32 + lane] = acc;
}

// ---------------- log_softmax over 64 classes, in place ----------------
__global__ void logsoftmax64_kernel(float* __restrict__ out, int n) {
    int row = blockIdx.x * 8 + (threadIdx.x >> 5);
    int lane = threadIdx.x & 31;
    if (row >= n) return;
    float* p = out + (size_t)row * 64;
    float a = p[lane], b = p[lane + 32];
    float mx = fmaxf(a, b);
#pragma unroll
    for (int d = 16; d; d >>= 1) mx = fmaxf(mx, __shfl_xor_sync(0xFFFFFFFFu, mx, d));
    float s = __expf(a - mx) + __expf(b - mx);
#pragma unroll
    for (int d = 16; d; d >>= 1) s += __shfl_xor_sync(0xFFFFFFFFu, s, d);
    float lse = mx + __logf(s);
    p[lane] = a - lse;
    p[lane + 32] = b - lse;
}

// ---------------- launch ----------------
extern "C" void kernel_launch(void* const* d_in, const int* in_sizes, int n_in,
                              void* d_out, int out_size) {
    const float* x     = (const float*)d_in[0];
    const int*   ei    = (const int*)  d_in[1];
    const float* ew    = (const float*)d_in[2];
    const float* w_in  = (const float*)d_in[3];
    const float* b_in  = (const float*)d_in[4];
    const float* ws1   = (const float*)d_in[5];
    const float* ws2   = (const float*)d_in[6];
    const float* w_out = (const float*)d_in[7];
    const float* b_out = (const float*)d_in[8];

    const int N = in_sizes[0] / HDIM;            // 50000
    const int E = in_sizes[2];                   // 640000
    const int L = in_sizes[5] / (HDIM * HDIM);   // 16
    const float ALPHA = 0.1f;
    const double LAMDA = 0.5;

    const int* erow = ei;
    const int* ecol = ei + E;

    float *deg, *dinv, *wc, *h0, *ag;
    __nv_bfloat16* hb;
    int *cnt, *off, *fill, *src;
    cudaGetSymbolAddress((void**)&deg,  g_deg);
    cudaGetSymbolAddress((void**)&dinv, g_dinv);
    cudaGetSymbolAddress((void**)&cnt,  g_cnt);
    cudaGetSymbolAddress((void**)&off,  g_off);
    cudaGetSymbolAddress((void**)&fill, g_fill);
    cudaGetSymbolAddress((void**)&src,  g_src);
    cudaGetSymbolAddress((void**)&wc,   g_wc);
    cudaGetSymbolAddress((void**)&hb,   g_hb);
    cudaGetSymbolAddress((void**)&h0,   g_h0);
    cudaGetSymbolAddress((void**)&ag,   g_ag);

    const int TB = 256;
    const int gN = (N + TB - 1) / TB;
    const int gE = (E + TB - 1) / TB;
    const int nb = (N + 1023) / 1024;            // 49 scan blocks

    // ---- graph normalization + CSC build ----
    init_kernel<<<gN, TB>>>(deg, cnt, N);
    edge_count_kernel<<<gE, TB>>>(erow, ecol, ew, deg, cnt, E);
    dinv_kernel<<<gN, TB>>>(deg, dinv, N);
    scan_block_kernel<<<nb, 1024>>>(cnt, off, N);
    scan_bsums_kernel<<<1, 32>>>(nb);
    scan_fixup_kernel<<<nb, 1024>>>(off, fill, N, nb);
    fill_edges_kernel<<<gE, TB>>>(erow, ecol, ew, dinv, fill, src, wc, E);
    fill_self_kernel<<<gN, TB>>>(dinv, fill, src, wc, N);

    // zero padding rows of h0/ag
    {
        int startElem = N * HDIM;
        int padElems = NFEAT_PAD - startElem;
        pad_kernel<<<(padElems + TB - 1) / TB, TB>>>(h0, ag, startElem, NFEAT_PAD);
    }

    const int gGemm = MAXN / BM;   // 391, covers padded rows

    // ---- input linear + relu; hb (bf16) and h0 (fp32) ----
    gemm_in<<<gGemm, 256>>>(x, w_in, b_in, hb, h0, N);

    // ---- GCNII layers: ag = A_hat@hb, then fused bf16 K=256 GEMM -> hb ----
    for (int i = 0; i < L; i++) {
        float beta = (float)log(LAMDA / (double)(i + 1) + 1.0);
        float cs = (1.0f - beta) * (1.0f - ALPHA);
        float ci = (1.0f - beta) * ALPHA;
        agg_kernel<<<(N * 32 + 255) / 256, 256>>>(hb, off, src, wc, ag, N);
        gemm_layer_tc<<<gGemm, 256>>>(ag, h0,
                                      ws1 + (size_t)i * HDIM * HDIM,
                                      ws2 + (size_t)i * HDIM * HDIM,
                                      hb, cs, ci, beta);
    }

    // ---- output linear + log_softmax ----
    float* outp = (float*)d_out;
    gemm_out<<<gGemm, 256>>>(hb, w_out, b_out, outp, N);
    logsoftmax64_kernel<<<(N + 7) / 8, 256>>>(outp, N);
}

// round 17
// speedup vs baseline: 2.1543x; 1.0102x over previous
#include <cuda_runtime.h>
#include <cuda_bf16.h>
#include <mma.h>
#include <math.h>
#include <cstdint>

using namespace nvcuda;

// ---------------- problem constants ----------------
#define HDIM 128                 // F_IN == H == 128
#define MAXN 50048               // 391 * 128, padded node count
#define MAXNNZ 700000
#define NFEAT_PAD (MAXN * HDIM)

// ---------------- device scratch (allocation-free) ----------------
__device__ float g_deg[MAXN];
__device__ float g_dinv[MAXN];
__device__ int   g_cnt[MAXN];
__device__ int   g_off[MAXN + 1];
__device__ int   g_fill[MAXN];
__device__ int   g_src[MAXNNZ];
__device__ float g_wc[MAXNNZ];
__device__ __nv_bfloat16 g_hb[NFEAT_PAD];   // bf16 inter-layer state (agg input)
__device__ float g_h0[NFEAT_PAD];
__device__ float g_ag[NFEAT_PAD];
__device__ int   g_bsum[64];
__device__ int   g_boff[65];

// ---------------- graph preprocessing ----------------
__global__ void init_kernel(float* deg, int* cnt, int n) {
    int i = blockIdx.x * blockDim.x + threadIdx.x;
    if (i < n) { deg[i] = 1.0f; cnt[i] = 1; }   // self-loop weight 1, self in-edge
}

__global__ void edge_count_kernel(const int* __restrict__ row, const int* __restrict__ col,
                                  const float* __restrict__ w, float* deg, int* cnt, int E) {
    int e = blockIdx.x * blockDim.x + threadIdx.x;
    if (e < E) {
        atomicAdd(&deg[row[e]], w[e]);
        atomicAdd(&cnt[col[e]], 1);
    }
}

__global__ void dinv_kernel(const float* __restrict__ deg, float* dinv, int n) {
    int i = blockIdx.x * blockDim.x + threadIdx.x;
    if (i < n) dinv[i] = rsqrtf(deg[i]);   // deg >= 1 always
}

// ---- multi-block exclusive scan: per-block scan -> scan of block sums -> fixup ----
__global__ void scan_block_kernel(const int* __restrict__ cnt, int* off, int n) {
    __shared__ int sm[1024];
    int i = blockIdx.x * 1024 + threadIdx.x;
    int v = (i < n) ? cnt[i] : 0;
    sm[threadIdx.x] = v;
    __syncthreads();
#pragma unroll
    for (int d = 1; d < 1024; d <<= 1) {
        int t = (threadIdx.x >= d) ? sm[threadIdx.x - d] : 0;
        __syncthreads();
        sm[threadIdx.x] += t;
        __syncthreads();
    }
    if (i < n) off[i] = sm[threadIdx.x] - v;     // exclusive within block
    if (threadIdx.x == 1023) g_bsum[blockIdx.x] = sm[1023];
}

__global__ void scan_bsums_kernel(int nb) {
    if (threadIdx.x == 0) {
        int acc = 0;
        for (int b = 0; b < nb; b++) { g_boff[b] = acc; acc += g_bsum[b]; }
        g_boff[nb] = acc;
    }
}

__global__ void scan_fixup_kernel(int* off, int* fill, int n, int nb) {
    int i = blockIdx.x * 1024 + threadIdx.x;
    if (i < n) {
        int o = off[i] + g_boff[blockIdx.x];
        off[i] = o; fill[i] = o;
    }
    if (i == 0) off[n] = g_boff[nb];
}

__global__ void fill_edges_kernel(const int* __restrict__ row, const int* __restrict__ col,
                                  const float* __restrict__ w, const float* __restrict__ dinv,
                                  int* fill, int* srcv, float* wcsc, int E) {
    int e = blockIdx.x * blockDim.x + threadIdx.x;
    if (e < E) {
        int r = row[e], c = col[e];
        int p = atomicAdd(&fill[c], 1);
        srcv[p] = r;
        wcsc[p] = dinv[r] * w[e] * dinv[c];
    }
}

__global__ void fill_self_kernel(const float* __restrict__ dinv, int* fill,
                                 int* srcv, float* wcsc, int n) {
    int i = blockIdx.x * blockDim.x + threadIdx.x;
    if (i < n) {
        int p = atomicAdd(&fill[i], 1);
        srcv[p] = i;
        wcsc[p] = dinv[i] * dinv[i];
    }
}

// zero padding rows [N, MAXN) of h0 and ag so guard-free GEMMs read zeros
__global__ void pad_kernel(float* h0, float* ag, int startElem, int totalElem) {
    int i = blockIdx.x * blockDim.x + threadIdx.x + startElem;
    if (i < totalElem) { h0[i] = 0.0f; ag[i] = 0.0f; }
}

// ---------------- fp32 SGEMM tiles (input / output linears) ----------------
#define BM 128
#define BN 128
#define BK 8
#define TM 8
#define TN 8

// ---- input linear: h0(fp32) = hb(bf16) = relu(x @ w_in + b), guarded ----
__global__ void __launch_bounds__(256, 2)
gemm_in(const float* __restrict__ A, const float* __restrict__ W,
        const float* __restrict__ bias, __nv_bfloat16* __restrict__ hb,
        float* __restrict__ h0, int M) {
    __shared__ float As[BK][BM];
    __shared__ float Bs[BK][BN];
    const int tid = threadIdx.x;
    const int tx = tid & 15, ty = tid >> 4;
    const int m0 = blockIdx.x * BM;
    const int arow = tid >> 1, acol4 = (tid & 1) * 4;
    const int brow = tid >> 5, bcol4 = (tid & 31) * 4;

    float acc[TM][TN];
#pragma unroll
    for (int i = 0; i < TM; i++)
#pragma unroll
        for (int j = 0; j < TN; j++) acc[i][j] = 0.0f;

    for (int k0 = 0; k0 < HDIM; k0 += BK) {
        float4 av = make_float4(0.f, 0.f, 0.f, 0.f);
        int am = m0 + arow;
        if (am < M) av = *reinterpret_cast<const float4*>(A + (size_t)am * HDIM + k0 + acol4);
        As[acol4 + 0][arow] = av.x; As[acol4 + 1][arow] = av.y;
        As[acol4 + 2][arow] = av.z; As[acol4 + 3][arow] = av.w;

        float4 bv = *reinterpret_cast<const float4*>(W + (size_t)(k0 + brow) * HDIM + bcol4);
        Bs[brow][bcol4 + 0] = bv.x; Bs[brow][bcol4 + 1] = bv.y;
        Bs[brow][bcol4 + 2] = bv.z; Bs[brow][bcol4 + 3] = bv.w;
        __syncthreads();

#pragma unroll
        for (int kk = 0; kk < BK; kk++) {
            float ra[TM], rb[TN];
#pragma unroll
            for (int i = 0; i < TM; i++) ra[i] = As[kk][ty * TM + i];
#pragma unroll
            for (int j = 0; j < TN; j++) rb[j] = Bs[kk][tx * TN + j];
#pragma unroll
            for (int i = 0; i < TM; i++)
#pragma unroll
                for (int j = 0; j < TN; j++) acc[i][j] += ra[i] * rb[j];
        }
        __syncthreads();
    }

    float b0[TN];
#pragma unroll
    for (int j = 0; j < TN; j++) b0[j] = bias[tx * TN + j];

#pragma unroll
    for (int i = 0; i < TM; i++) {
        int m = m0 + ty * TM + i;
        if (m >= M) continue;
        float o[8];
#pragma unroll
        for (int j = 0; j < TN; j++) o[j] = fmaxf(acc[i][j] + b0[j], 0.0f);
        float4* p2 = reinterpret_cast<float4*>(h0 + (size_t)m * HDIM + tx * TN);
        p2[0] = make_float4(o[0], o[1], o[2], o[3]);
        p2[1] = make_float4(o[4], o[5], o[6], o[7]);
        union { __nv_bfloat162 p[4]; uint4 u; } pk;
#pragma unroll
        for (int q = 0; q < 4; q++)
            pk.p[q] = __halves2bfloat162(__float2bfloat16(o[q * 2]),
                                         __float2bfloat16(o[q * 2 + 1]));
        *reinterpret_cast<uint4*>(hb + (size_t)m * HDIM + tx * TN) = pk.u;
    }
}

// ---- output linear: out[M,64] = hb(bf16) @ w_out + b_out ----
__global__ void __launch_bounds__(256, 2)
gemm_out(const __nv_bfloat16* __restrict__ A, const float* __restrict__ W,
         const float* __restrict__ bias, float* __restrict__ out, int M) {
    __shared__ float As[BK][BM];
    __shared__ float Bs[BK][BN];
    const int tid = threadIdx.x;
    const int tx = tid & 15, ty = tid >> 4;
    const int m0 = blockIdx.x * BM;
    const int arow = tid >> 1, acol4 = (tid & 1) * 4;
    const int brow = tid >> 5, bcol4 = (tid & 31) * 4;
    const int Nn = 64;

    float acc[TM][TN];
#pragma unroll
    for (int i = 0; i < TM; i++)
#pragma unroll
        for (int j = 0; j < TN; j++) acc[i][j] = 0.0f;

    for (int k0 = 0; k0 < HDIM; k0 += BK) {
        uint2 v = *reinterpret_cast<const uint2*>(A + (size_t)(m0 + arow) * HDIM + k0 + acol4);
        float2 f01 = __bfloat1622float2(*reinterpret_cast<const __nv_bfloat162*>(&v.x));
        float2 f23 = __bfloat1622float2(*reinterpret_cast<const __nv_bfloat162*>(&v.y));
        As[acol4 + 0][arow] = f01.x; As[acol4 + 1][arow] = f01.y;
        As[acol4 + 2][arow] = f23.x; As[acol4 + 3][arow] = f23.y;

        float4 bv = make_float4(0.f, 0.f, 0.f, 0.f);
        if (bcol4 < Nn) bv = *reinterpret_cast<const float4*>(W + (size_t)(k0 + brow) * Nn + bcol4);
        Bs[brow][bcol4 + 0] = bv.x; Bs[brow][bcol4 + 1] = bv.y;
        Bs[brow][bcol4 + 2] = bv.z; Bs[brow][bcol4 + 3] = bv.w;
        __syncthreads();

#pragma unroll
        for (int kk = 0; kk < BK; kk++) {
            float ra[TM], rb[TN];
#pragma unroll
            for (int i = 0; i < TM; i++) ra[i] = As[kk][ty * TM + i];
#pragma unroll
            for (int j = 0; j < TN; j++) rb[j] = Bs[kk][tx * TN + j];
#pragma unroll
            for (int i = 0; i < TM; i++)
#pragma unroll
                for (int j = 0; j < TN; j++) acc[i][j] += ra[i] * rb[j];
        }
        __syncthreads();
    }

    if (tx < 8) {   // only columns < 64
        float b0[TN];
#pragma unroll
        for (int j = 0; j < TN; j++) b0[j] = bias[tx * TN + j];
#pragma unroll
        for (int i = 0; i < TM; i++) {
            int m = m0 + ty * TM + i;
            if (m >= M) continue;
            float4 o0, o1;
            o0.x = acc[i][0] + b0[0]; o0.y = acc[i][1] + b0[1];
            o0.z = acc[i][2] + b0[2]; o0.w = acc[i][3] + b0[3];
            o1.x = acc[i][4] + b0[4]; o1.y = acc[i][5] + b0[5];
            o1.z = acc[i][6] + b0[6]; o1.w = acc[i][7] + b0[7];
            float4* p = reinterpret_cast<float4*>(out + (size_t)m * Nn + tx * TN);
            p[0] = o0; p[1] = o1;
        }
    }
}

// ---------------- bf16 tensor-core fused layer GEMM (register-prefetch pipeline) ----
// hb_out(bf16) = relu( cs*ag + ci*h0 + beta*( ag@W1 + h0@W2 ) )   (padded M)
#define TCA_LD 24    // bf16 elems per A row (16 + 8 pad), 48 B (mult of 16)
#define TCB_LD 136   // bf16 elems per B row (128 + 8 pad), 272 B (mult of 16)
#define SLDM 20      // epilogue staging leading dim (floats)

__global__ void __launch_bounds__(256)
gemm_layer_tc(const float* __restrict__ ag, const float* __restrict__ h0,
              const float* __restrict__ W1, const float* __restrict__ W2,
              __nv_bfloat16* __restrict__ hb, float cs, float ci, float beta) {
    __shared__ __align__(16) unsigned char smraw[(128 * TCA_LD + 16 * TCB_LD) * 2];
    __nv_bfloat16* sA = reinterpret_cast<__nv_bfloat16*>(smraw);
    __nv_bfloat16* sB = reinterpret_cast<__nv_bfloat16*>(smraw) + 128 * TCA_LD;

    const int tid = threadIdx.x;
    const int wid = tid >> 5;
    const int lane = tid & 31;
    const int warp_m = wid >> 1;          // 0..3
    const int warp_n = wid & 1;           // 0..1
    const int m0 = blockIdx.x * 128;

    // ---- init accumulators with the exact-fp32 residual: cs*ag + ci*h0 ----
    wmma::fragment<wmma::accumulator, 16, 16, 16, float> C[2][4];
#pragma unroll
    for (int mi = 0; mi < 2; mi++) {
        const size_t rbase = (size_t)(m0 + warp_m * 32 + mi * 16) * HDIM;
#pragma unroll
        for (int ni = 0; ni < 4; ni++) {
            const int coff = warp_n * 64 + ni * 16;
            wmma::fragment<wmma::accumulator, 16, 16, 16, float> Ra, Rb;
            wmma::load_matrix_sync(Ra, ag + rbase + coff, HDIM, wmma::mem_row_major);
            wmma::load_matrix_sync(Rb, h0 + rbase + coff, HDIM, wmma::mem_row_major);
#pragma unroll
            for (int t = 0; t < Ra.num_elements; t++)
                C[mi][ni].x[t] = cs * Ra.x[t] + ci * Rb.x[t];
        }
    }

    // tile-load thread mapping
    const int a_row = tid >> 1, a_seg = (tid & 1) * 8;        // A: 2 thr/row, 8 floats
    const int b_row = tid >> 4, b_col = (tid & 15) * 8;       // B: 16 thr/row, 8 floats

    float ar[8], br[8];
    // prologue: load k-tile 0 (half 0: A=ag, W=W1) into registers
    {
        const float* Asrc = ag + (size_t)(m0 + a_row) * HDIM + a_seg;
        float4 v0 = reinterpret_cast<const float4*>(Asrc)[0];
        float4 v1 = reinterpret_cast<const float4*>(Asrc)[1];
        ar[0] = v0.x; ar[1] = v0.y; ar[2] = v0.z; ar[3] = v0.w;
        ar[4] = v1.x; ar[5] = v1.y; ar[6] = v1.z; ar[7] = v1.w;
        const float* Bsrc = W1 + (size_t)b_row * HDIM + b_col;
        float4 w0 = reinterpret_cast<const float4*>(Bsrc)[0];
        float4 w1 = reinterpret_cast<const float4*>(Bsrc)[1];
        br[0] = w0.x; br[1] = w0.y; br[2] = w0.z; br[3] = w0.w;
        br[4] = w1.x; br[5] = w1.y; br[6] = w1.z; br[7] = w1.w;
    }

#pragma unroll 1
    for (int kt = 0; kt < 16; kt++) {
        __syncthreads();   // previous tile's consumers done with smem
        // STS: convert regs -> bf16 smem (beta folded into B)
        {
            union { __nv_bfloat162 p[4]; uint4 u; } pa;
#pragma unroll
            for (int q = 0; q < 4; q++)
                pa.p[q] = __halves2bfloat162(__float2bfloat16(ar[q * 2]),
                                             __float2bfloat16(ar[q * 2 + 1]));
            *reinterpret_cast<uint4*>(sA + a_row * TCA_LD + a_seg) = pa.u;
            union { __nv_bfloat162 p[4]; uint4 u; } pb;
#pragma unroll
            for (int q = 0; q < 4; q++)
                pb.p[q] = __halves2bfloat162(__float2bfloat16(beta * br[q * 2]),
                                             __float2bfloat16(beta * br[q * 2 + 1]));
            *reinterpret_cast<uint4*>(sB + b_row * TCB_LD + b_col) = pb.u;
        }
        // prefetch k-tile kt+1 into registers (hides under compute below)
        if (kt + 1 < 16) {
            int nk = kt + 1;
            int half = nk >> 3;
            int k0 = (nk & 7) * 16;
            const float* Abase = half ? h0 : ag;
            const float* Wbase = half ? W2 : W1;
            const float* Asrc = Abase + (size_t)(m0 + a_row) * HDIM + k0 + a_seg;
            float4 v0 = reinterpret_cast<const float4*>(Asrc)[0];
            float4 v1 = reinterpret_cast<const float4*>(Asrc)[1];
            ar[0] = v0.x; ar[1] = v0.y; ar[2] = v0.z; ar[3] = v0.w;
            ar[4] = v1.x; ar[5] = v1.y; ar[6] = v1.z; ar[7] = v1.w;
            const float* Bsrc = Wbase + (size_t)(k0 + b_row) * HDIM + b_col;
            float4 w0 = reinterpret_cast<const float4*>(Bsrc)[0];
            float4 w1 = reinterpret_cast<const float4*>(Bsrc)[1];
            br[0] = w0.x; br[1] = w0.y; br[2] = w0.z; br[3] = w0.w;
            br[4] = w1.x; br[5] = w1.y; br[6] = w1.z; br[7] = w1.w;
        }
        __syncthreads();   // smem tile kt ready

        // compute tile kt: one k16 mma per (mi, ni)
        wmma::fragment<wmma::matrix_a, 16, 16, 16, __nv_bfloat16, wmma::row_major> a[2];
#pragma unroll
        for (int mi = 0; mi < 2; mi++)
            wmma::load_matrix_sync(a[mi], sA + (warp_m * 32 + mi * 16) * TCA_LD, TCA_LD);
#pragma unroll
        for (int ni = 0; ni < 4; ni++) {
            wmma::fragment<wmma::matrix_b, 16, 16, 16, __nv_bfloat16, wmma::row_major> b;
            wmma::load_matrix_sync(b, sB + warp_n * 64 + ni * 16, TCB_LD);
#pragma unroll
            for (int mi = 0; mi < 2; mi++)
                wmma::mma_sync(C[mi][ni], a[mi], b, C[mi][ni]);
        }
    }

    // ---- epilogue: stage each frag in warp-private smem, relu, emit bf16 ----
    __syncthreads();                       // all warps done reading sA/sB
    float* stage = reinterpret_cast<float*>(smraw) + wid * (16 * SLDM);
    const int r = lane >> 1;
    const int cseg = (lane & 1) * 8;
#pragma unroll
    for (int mi = 0; mi < 2; mi++) {
#pragma unroll
        for (int ni = 0; ni < 4; ni++) {
            wmma::store_matrix_sync(stage, C[mi][ni], SLDM, wmma::mem_row_major);
            __syncwarp();
            const float* sp = stage + r * SLDM + cseg;
            union { __nv_bfloat162 p[4]; uint4 u; } pk;
#pragma unroll
            for (int q = 0; q < 4; q++) {
                float f0 = fmaxf(sp[q * 2 + 0], 0.0f);
                float f1 = fmaxf(sp[q * 2 + 1], 0.0f);
                pk.p[q] = __halves2bfloat162(__float2bfloat16(f0), __float2bfloat16(f1));
            }
            size_t row = (size_t)(m0 + warp_m * 32 + mi * 16 + r);
            int col = warp_n * 64 + ni * 16 + cseg;
            *reinterpret_cast<uint4*>(hb + row * HDIM + col) = pk.u;
            __syncwarp();
        }
    }
}

// ---------------- atomic-free CSC aggregation (half-warp per node) --------------
// ag[c,:] = sum_j wc[j] * hb[src[j],:]
// 16 threads per node; each lane covers 8 bf16 (one uint4, 16 B); 4-edge unroll.
__global__ void agg_kernel(const __nv_bfloat16* __restrict__ hb,
                           const int* __restrict__ off, const int* __restrict__ src,
                           const float* __restrict__ wc, float* __restrict__ ag, int n) {
    int node = (blockIdx.x * blockDim.x + threadIdx.x) >> 4;
    int l16 = threadIdx.x & 15;
    if (node >= n) return;
    int s = off[node], e = off[node + 1];
    const uint4* H = reinterpret_cast<const uint4*>(hb);   // 16 uint4 per row
    float acc[8];
#pragma unroll
    for (int q = 0; q < 8; q++) acc[q] = 0.0f;

    int j = s;
    for (; j + 3 < e; j += 4) {
        int   si[4];
        float wi[4];
        uint4 vv[4];
#pragma unroll
        for (int u = 0; u < 4; u++) { si[u] = src[j + u]; wi[u] = wc[j + u]; }
#pragma unroll
        for (int u = 0; u < 4; u++) vv[u] = H[(size_t)si[u] * 16 + l16];
#pragma unroll
        for (int u = 0; u < 4; u++) {
            float2 f0 = __bfloat1622float2(*reinterpret_cast<const __nv_bfloat162*>(&vv[u].x));
            float2 f1 = __bfloat1622float2(*reinterpret_cast<const __nv_bfloat162*>(&vv[u].y));
            float2 f2 = __bfloat1622float2(*reinterpret_cast<const __nv_bfloat162*>(&vv[u].z));
            float2 f3 = __bfloat1622float2(*reinterpret_cast<const __nv_bfloat162*>(&vv[u].w));
            float w = wi[u];
            acc[0] += w * f0.x; acc[1] += w * f0.y;
            acc[2] += w * f1.x; acc[3] += w * f1.y;
            acc[4] += w * f2.x; acc[5] += w * f2.y;
            acc[6] += w * f3.x; acc[7] += w * f3.y;
        }
    }
    for (; j < e; j++) {
        float w = wc[j];
        uint4 v = H[(size_t)src[j] * 16 + l16];
        float2 f0 = __bfloat1622float2(*reinterpret_cast<const __nv_bfloat162*>(&v.x));
        float2 f1 = __bfloat1622float2(*reinterpret_cast<const __nv_bfloat162*>(&v.y));
        float2 f2 = __bfloat1622float2(*reinterpret_cast<const __nv_bfloat162*>(&v.z));
        float2 f3 = __bfloat1622float2(*reinterpret_cast<const __nv_bfloat162*>(&v.w));
        acc[0] += w * f0.x; acc[1] += w * f0.y;
        acc[2] += w * f1.x; acc[3] += w * f1.y;
        acc[4] += w * f2.x; acc[5] += w * f2.y;
        acc[6] += w * f3.x; acc[7] += w * f3.y;
    }

    float4* out = reinterpret_cast<float4*>(ag + (size_t)node * HDIM + l16 * 8);
    out[0] = make_float4(acc[0], acc[1], acc[2], acc[3]);
    out[1] = make_float4(acc[4], acc[5], acc[6], acc[7]);
}

// ---------------- log_softmax over 64 classes, in place ----------------
__global__ void logsoftmax64_kernel(float* __restrict__ out, int n) {
    int row = blockIdx.x * 8 + (threadIdx.x >> 5);
    int lane = threadIdx.x & 31;
    if (row >= n) return;
    float* p = out + (size_t)row * 64;
    float a = p[lane], b = p[lane + 32];
    float mx = fmaxf(a, b);
#pragma unroll
    for (int d = 16; d; d >>= 1) mx = fmaxf(mx, __shfl_xor_sync(0xFFFFFFFFu, mx, d));
    float s = __expf(a - mx) + __expf(b - mx);
#pragma unroll
    for (int d = 16; d; d >>= 1) s += __shfl_xor_sync(0xFFFFFFFFu, s, d);
    float lse = mx + __logf(s);
    p[lane] = a - lse;
    p[lane + 32] = b - lse;
}

// ---------------- launch ----------------
extern "C" void kernel_launch(void* const* d_in, const int* in_sizes, int n_in,
                              void* d_out, int out_size) {
    const float* x     = (const float*)d_in[0];
    const int*   ei    = (const int*)  d_in[1];
    const float* ew    = (const float*)d_in[2];
    const float* w_in  = (const float*)d_in[3];
    const float* b_in  = (const float*)d_in[4];
    const float* ws1   = (const float*)d_in[5];
    const float* ws2   = (const float*)d_in[6];
    const float* w_out = (const float*)d_in[7];
    const float* b_out = (const float*)d_in[8];

    const int N = in_sizes[0] / HDIM;            // 50000
    const int E = in_sizes[2];                   // 640000
    const int L = in_sizes[5] / (HDIM * HDIM);   // 16
    const float ALPHA = 0.1f;
    const double LAMDA = 0.5;

    const int* erow = ei;
    const int* ecol = ei + E;

    float *deg, *dinv, *wc, *h0, *ag;
    __nv_bfloat16* hb;
    int *cnt, *off, *fill, *src;
    cudaGetSymbolAddress((void**)&deg,  g_deg);
    cudaGetSymbolAddress((void**)&dinv, g_dinv);
    cudaGetSymbolAddress((void**)&cnt,  g_cnt);
    cudaGetSymbolAddress((void**)&off,  g_off);
    cudaGetSymbolAddress((void**)&fill, g_fill);
    cudaGetSymbolAddress((void**)&src,  g_src);
    cudaGetSymbolAddress((void**)&wc,   g_wc);
    cudaGetSymbolAddress((void**)&hb,   g_hb);
    cudaGetSymbolAddress((void**)&h0,   g_h0);
    cudaGetSymbolAddress((void**)&ag,   g_ag);

    const int TB = 256;
    const int gN = (N + TB - 1) / TB;
    const int gE = (E + TB - 1) / TB;
    const int nb = (N + 1023) / 1024;            // 49 scan blocks

    // ---- graph normalization + CSC build ----
    init_kernel<<<gN, TB>>>(deg, cnt, N);
    edge_count_kernel<<<gE, TB>>>(erow, ecol, ew, deg, cnt, E);
    dinv_kernel<<<gN, TB>>>(deg, dinv, N);
    scan_block_kernel<<<nb, 1024>>>(cnt, off, N);
    scan_bsums_kernel<<<1, 32>>>(nb);
    scan_fixup_kernel<<<nb, 1024>>>(off, fill, N, nb);
    fill_edges_kernel<<<gE, TB>>>(erow, ecol, ew, dinv, fill, src, wc, E);
    fill_self_kernel<<<gN, TB>>>(dinv, fill, src, wc, N);

    // zero padding rows of h0/ag
    {
        int startElem = N * HDIM;
        int padElems = NFEAT_PAD - startElem;
        pad_kernel<<<(padElems + TB - 1) / TB, TB>>>(h0, ag, startElem, NFEAT_PAD);
    }

    const int gGemm = MAXN / BM;   // 391, covers padded rows

    // ---- input linear + relu; hb (bf16) and h0 (fp32) ----
    gemm_in<<<gGemm, 256>>>(x, w_in, b_in, hb, h0, N);

    // ---- GCNII layers: ag = A_hat@hb, then fused bf16 K=256 GEMM -> hb ----
    for (int i = 0; i < L; i++) {
        float beta = (float)log(LAMDA / (double)(i + 1) + 1.0);
        float cs = (1.0f - beta) * (1.0f - ALPHA);
        float ci = (1.0f - beta) * ALPHA;
        agg_kernel<<<(N * 16 + 255) / 256, 256>>>(hb, off, src, wc, ag, N);
        gemm_layer_tc<<<gGemm, 256>>>(ag, h0,
                                      ws1 + (size_t)i * HDIM * HDIM,
                                      ws2 + (size_t)i * HDIM * HDIM,
                                      hb, cs, ci, beta);
    }

    // ---- output linear + log_softmax ----
    float* outp = (float*)d_out;
    gemm_out<<<gGemm, 256>>>(hb, w_out, b_out, outp, N);
    logsoftmax64_kernel<<<(N + 7) / 8, 256>>>(outp, N);
}